// round 4
// baseline (speedup 1.0000x reference)
#include <cuda_runtime.h>
#include <cuda_bf16.h>
#include <cstdint>
#include <cstddef>

// ---------------------------------------------------------------------------
// Problem constants
// ---------------------------------------------------------------------------
#define BATCH   4096
#define IND     512
#define OUTD    512
#define ROWLEN  514            // P + IND
#define D2      25             // D^P
#define KREAL   12800          // IND * D2
#define KPAD    12864          // KREAL + 64 (bias block, zero padded) = 201*64
#define NITER   201            // KPAD / 64
#define STAGES  4
#define TILE_M  128
#define TILE_N  128
#define STAGE_BYTES 32768      // 16KB A + 16KB B (128 rows x 128B each)
#define SMEM_GEMM (STAGES * STAGE_BYTES)   // 131072

// Scratch (device globals — no allocation allowed)
__device__ __nv_bfloat16 g_A[(size_t)BATCH * KPAD];   // Z matrix, bf16, K-major
__device__ __nv_bfloat16 g_W[(size_t)OUTD * KPAD];    // packed weight+bias, K-major

// ---------------------------------------------------------------------------
// PTX helpers (base sm_103 ISA only: cp.async, ldmatrix, mma.sync)
// ---------------------------------------------------------------------------
static __device__ __forceinline__ uint32_t smem_u32(const void* p) {
    uint32_t a;
    asm("{ .reg .u64 t; cvta.to.shared.u64 t, %1; cvt.u32.u64 %0, t; }"
        : "=r"(a) : "l"(p));
    return a;
}

static __device__ __forceinline__ void cp_async16(uint32_t sdst, const void* gsrc) {
    asm volatile("{ .reg .u64 gp; cvta.to.global.u64 gp, %1;"
                 "  cp.async.cg.shared.global [%0], [gp], 16; }"
                 :: "r"(sdst), "l"(gsrc) : "memory");
}

static __device__ __forceinline__ void ldsm_x4(uint32_t* r, uint32_t addr) {
    asm volatile("ldmatrix.sync.aligned.m8n8.x4.shared.b16 {%0,%1,%2,%3}, [%4];"
                 : "=r"(r[0]), "=r"(r[1]), "=r"(r[2]), "=r"(r[3]) : "r"(addr));
}

static __device__ __forceinline__ void mma16816(float* c, const uint32_t* a,
                                                uint32_t b0, uint32_t b1) {
    asm volatile(
        "mma.sync.aligned.m16n8k16.row.col.f32.bf16.bf16.f32 "
        "{%0,%1,%2,%3}, {%4,%5,%6,%7}, {%8,%9}, {%0,%1,%2,%3};"
        : "+f"(c[0]), "+f"(c[1]), "+f"(c[2]), "+f"(c[3])
        : "r"(a[0]), "r"(a[1]), "r"(a[2]), "r"(a[3]), "r"(b0), "r"(b1));
}

// ---------------------------------------------------------------------------
// Kernel 1: basis + kb, build A = Z (bf16), write x_treat to output
// grid = BATCH, block = 128
// ---------------------------------------------------------------------------
static __device__ __forceinline__ void basis5(float t, float* u) {
    u[0] = 1.0f;
    u[1] = t;
    u[2] = t * t;
    float a = t - 0.33f; a = a > 0.0f ? a : 0.0f; u[3] = a * a;
    float b = t - 0.66f; b = b > 0.0f ? b : 0.0f; u[4] = b * b;
}

__global__ void prep_A_kernel(const float* __restrict__ x, float* __restrict__ out) {
    const int b = blockIdx.x;
    const int t = threadIdx.x;
    const float* xr = x + (size_t)b * ROWLEN;
    const float t0 = xr[0], t1 = xr[1];

    float u[5], v[5];
    basis5(t0, u);
    basis5(t1, v);
    float kb[25];
#pragma unroll
    for (int i = 0; i < 5; ++i)
#pragma unroll
        for (int j = 0; j < 5; ++j)
            kb[i * 5 + j] = u[i] * v[j];

    if (t < 2) out[(size_t)b * ROWLEN + t] = (t == 0) ? t0 : t1;

    float xf[4];
#pragma unroll
    for (int j = 0; j < 4; ++j) xf[j] = xr[2 + t + j * 128];

    __nv_bfloat16* A = g_A + (size_t)b * KPAD;
#pragma unroll
    for (int d = 0; d < 25; ++d) {
        const float s = kb[d];
#pragma unroll
        for (int j = 0; j < 4; ++j)
            A[d * 512 + t + j * 128] = __float2bfloat16(s * xf[j]);
    }
    // bias block: kb entries then zeros (cols 12800..12863)
    if (t < 64) A[KREAL + t] = __float2bfloat16(t < 25 ? kb[t] : 0.0f);
}

// ---------------------------------------------------------------------------
// Kernel 2: pack weight (IND,OUTD,25) -> g_W[o][d*512+i] bf16, append bias rows
// grid = OUTD, block = 128, dynamic smem = IND*D2*2 bytes (51200)
// ---------------------------------------------------------------------------
__global__ void pack_W_kernel(const float* __restrict__ w, const float* __restrict__ bias) {
    extern __shared__ __nv_bfloat16 sw[];   // IND*D2 elements
    const int o = blockIdx.x;

    for (int idx = threadIdx.x; idx < IND * D2; idx += blockDim.x) {
        const int i = idx / D2;
        const int d = idx - i * D2;
        sw[idx] = __float2bfloat16(w[(size_t)i * (OUTD * D2) + o * D2 + d]);
    }
    __syncthreads();

    __nv_bfloat16* dst = g_W + (size_t)o * KPAD;
    for (int k = threadIdx.x; k < KPAD; k += blockDim.x) {
        __nv_bfloat16 val;
        if (k < KREAL) {
            const int d = k >> 9;
            const int i = k & 511;
            val = sw[i * D2 + d];
        } else if (k < KREAL + D2) {
            val = __float2bfloat16(bias[o * D2 + (k - KREAL)]);
        } else {
            val = __float2bfloat16(0.0f);
        }
        dst[k] = val;
    }
}

// ---------------------------------------------------------------------------
// Kernel 3: mma.sync (HMMA) GEMM. 128x128 CTA tile, 256 threads (8 warps).
// Warps 0-3: 2x2 spatial grid of 64x64 warp tiles, even K-chunks.
// Warps 4-7: same tiles, odd K-chunks. Partials reduced through smem at end.
// 4-stage cp.async pipeline, 64-K chunks, SW128-swizzled smem, ldmatrix feeds.
// grid = (32, 4), block = 256
// ---------------------------------------------------------------------------
__global__ void __launch_bounds__(256, 1)
gemm_hmma_kernel(float* __restrict__ out)
{
    extern __shared__ char smem[];
    const uint32_t sb = smem_u32(smem);
    const int tid  = threadIdx.x;
    const int wid  = tid >> 5;
    const int lid  = tid & 31;
    const int m0   = blockIdx.x * TILE_M;
    const int n0   = blockIdx.y * TILE_N;
    const int wq   = wid & 3;        // spatial warp 0..3
    const int half = wid >> 2;       // k-split half (0: even chunks, 1: odd)
    const int wm   = wq >> 1;        // 0..1
    const int wn   = wq & 1;         // 0..1

    // ---- producer geometry: thread -> (row, 16B-group), warp covers 4 rows x 128B
    const int  pr0 = tid >> 3;                 // 0..31
    const int  pg  = tid & 7;                  // 0..7
    const uint32_t psoff = (uint32_t)(pr0 * 128) +
                           ((uint32_t)(pg * 16) ^ (uint32_t)((pr0 & 7) << 4));
    const __nv_bfloat16* gA = g_A + (size_t)(m0 + pr0) * KPAD + pg * 8;
    const __nv_bfloat16* gB = g_W + (size_t)(n0 + pr0) * KPAD + pg * 8;

    // ---- consumer geometry (ldmatrix lane addressing, SW128 swizzle)
    const int arow = wm * 64 + (lid & 15);
    const uint32_t a_sz = (uint32_t)((arow & 7) << 4);
    const uint32_t a_k  = (uint32_t)((lid >> 4) * 16);
    const int brow = wn * 64 + ((lid >> 4) << 3) + (lid & 7);
    const uint32_t b_sz = (uint32_t)((lid & 7) << 4);
    const uint32_t b_k  = (uint32_t)(((lid >> 3) & 1) * 16);

    float c[4][8][4];
#pragma unroll
    for (int mt = 0; mt < 4; ++mt)
#pragma unroll
        for (int nt = 0; nt < 8; ++nt)
#pragma unroll
            for (int i = 0; i < 4; ++i) c[mt][nt][i] = 0.0f;

    // ---- prologue: fill stages 0..2
#pragma unroll
    for (int s = 0; s < STAGES - 1; ++s) {
        const uint32_t dst = sb + s * STAGE_BYTES + psoff;
        const size_t koff = (size_t)s * 64;
#pragma unroll
        for (int j = 0; j < 4; ++j)
            cp_async16(dst + j * 4096, gA + koff + (size_t)j * 32 * KPAD);
#pragma unroll
        for (int j = 0; j < 4; ++j)
            cp_async16(dst + 16384 + j * 4096, gB + koff + (size_t)j * 32 * KPAD);
        asm volatile("cp.async.commit_group;" ::: "memory");
    }

    // ---- main loop
    for (int it = 0; it < NITER; ++it) {
        const int s = it & (STAGES - 1);
        asm volatile("cp.async.wait_group %0;" :: "n"(STAGES - 2) : "memory");
        __syncthreads();

        const int fi = it + STAGES - 1;
        if (fi < NITER) {
            const uint32_t dst = sb + (fi & (STAGES - 1)) * STAGE_BYTES + psoff;
            const size_t koff = (size_t)fi * 64;
#pragma unroll
            for (int j = 0; j < 4; ++j)
                cp_async16(dst + j * 4096, gA + koff + (size_t)j * 32 * KPAD);
#pragma unroll
            for (int j = 0; j < 4; ++j)
                cp_async16(dst + 16384 + j * 4096, gB + koff + (size_t)j * 32 * KPAD);
        }
        asm volatile("cp.async.commit_group;" ::: "memory");

        if ((it & 1) == half) {
            const uint32_t stA = sb + s * STAGE_BYTES;
            const uint32_t stB = stA + 16384;
#pragma unroll
            for (int ks = 0; ks < 4; ++ks) {
                uint32_t a[4][4];
#pragma unroll
                for (int mt = 0; mt < 4; ++mt)
                    ldsm_x4(a[mt], stA + (uint32_t)(arow + mt * 16) * 128 +
                                   (((uint32_t)(ks * 32) + a_k) ^ a_sz));
                uint32_t b[4][4];
#pragma unroll
                for (int np = 0; np < 4; ++np)
                    ldsm_x4(b[np], stB + (uint32_t)(brow + np * 16) * 128 +
                                   (((uint32_t)(ks * 32) + b_k) ^ b_sz));
#pragma unroll
                for (int mt = 0; mt < 4; ++mt)
#pragma unroll
                    for (int np = 0; np < 4; ++np) {
                        mma16816(c[mt][2 * np],     a[mt], b[np][0], b[np][1]);
                        mma16816(c[mt][2 * np + 1], a[mt], b[np][2], b[np][3]);
                    }
            }
        }
    }

    // ---- k-split reduction through smem (stage buffers are dead now)
    __syncthreads();
    float* sred = reinterpret_cast<float*>(smem);
    if (half == 1) {
        float* dst = sred + (size_t)(wid - 4) * 4096 + lid;
#pragma unroll
        for (int mt = 0; mt < 4; ++mt)
#pragma unroll
            for (int nt = 0; nt < 8; ++nt)
#pragma unroll
                for (int i = 0; i < 4; ++i)
                    dst[(((mt * 8 + nt) * 4) + i) * 32] = c[mt][nt][i];
    }
    __syncthreads();

    if (half == 0) {
        const float* src = sred + (size_t)wid * 4096 + lid;
#pragma unroll
        for (int mt = 0; mt < 4; ++mt)
#pragma unroll
            for (int nt = 0; nt < 8; ++nt)
#pragma unroll
                for (int i = 0; i < 4; ++i)
                    c[mt][nt][i] += src[(((mt * 8 + nt) * 4) + i) * 32];

        // ---- fused ReLU epilogue
        const int rbase = m0 + wm * 64 + (lid >> 2);
        const int cbase = n0 + wn * 64 + ((lid & 3) << 1);
#pragma unroll
        for (int mt = 0; mt < 4; ++mt) {
            const int r = rbase + mt * 16;
#pragma unroll
            for (int nt = 0; nt < 8; ++nt) {
                const int cc = cbase + nt * 8;
                float2 v0, v1;
                v0.x = fmaxf(c[mt][nt][0], 0.0f);
                v0.y = fmaxf(c[mt][nt][1], 0.0f);
                v1.x = fmaxf(c[mt][nt][2], 0.0f);
                v1.y = fmaxf(c[mt][nt][3], 0.0f);
                *reinterpret_cast<float2*>(out + (size_t)r * ROWLEN + 2 + cc) = v0;
                *reinterpret_cast<float2*>(out + (size_t)(r + 8) * ROWLEN + 2 + cc) = v1;
            }
        }
    }
}

// ---------------------------------------------------------------------------
// Launch
// ---------------------------------------------------------------------------
extern "C" void kernel_launch(void* const* d_in, const int* in_sizes, int n_in,
                              void* d_out, int out_size)
{
    (void)in_sizes; (void)n_in; (void)out_size;
    const float* x    = (const float*)d_in[0];   // (4096, 514)
    const float* w    = (const float*)d_in[1];   // (512, 512, 25)
    const float* bias = (const float*)d_in[2];   // (512, 25)
    float* out = (float*)d_out;                  // (4096, 514)

    cudaFuncSetAttribute(gemm_hmma_kernel,
                         cudaFuncAttributeMaxDynamicSharedMemorySize, SMEM_GEMM);
    cudaFuncSetAttribute(pack_W_kernel,
                         cudaFuncAttributeMaxDynamicSharedMemorySize, IND * D2 * 2);

    prep_A_kernel<<<BATCH, 128>>>(x, out);
    pack_W_kernel<<<OUTD, 128, IND * D2 * 2>>>(w, bias);
    gemm_hmma_kernel<<<dim3(BATCH / TILE_M, OUTD / TILE_N), 256, SMEM_GEMM>>>(out);
}

// round 6
// speedup vs baseline: 1.0111x; 1.0111x over previous
#include <cuda_runtime.h>
#include <cuda_bf16.h>
#include <cstdint>
#include <cstddef>

// ---------------------------------------------------------------------------
// Problem constants
// ---------------------------------------------------------------------------
#define BATCH   4096
#define IND     512
#define OUTD    512
#define ROWLEN  514            // P + IND
#define D2      25             // D^P
#define KREAL   12800          // IND * D2
#define KPAD    12864          // KREAL + 64 (bias block) = 201*64
#define NITER   201            // KPAD / 64  (chunk c covers k = 64c .. 64c+63)
#define STAGES  4
#define TILE_M  128
#define TILE_N  128
#define STAGE_B 16384          // B tile per stage: 128 rows x 128B

// smem layout (bytes) for GEMM kernel
#define OFF_BST   0                       // B stages: 4 x 16384 = 65536
#define OFF_XF    65536                   // xf: 8 blocks x 16384 = 131072
#define OFF_KBP   196608                  // kb-pad ldmatrix tile: 16384
#define OFF_KBS   212992                  // kb scalars: 25*128*2 = 6400
#define SMEM_GEMM 219392

// Packed weight+bias, bf16 K-major: g_W[o][d*512+i], cols 12800..12824 = bias
__device__ __nv_bfloat16 g_W[(size_t)OUTD * KPAD];

// ---------------------------------------------------------------------------
// PTX helpers (base sm_103 ISA only)
// ---------------------------------------------------------------------------
static __device__ __forceinline__ uint32_t smem_u32(const void* p) {
    uint32_t a;
    asm("{ .reg .u64 t; cvta.to.shared.u64 t, %1; cvt.u32.u64 %0, t; }"
        : "=r"(a) : "l"(p));
    return a;
}

static __device__ __forceinline__ void cp_async16(uint32_t sdst, const void* gsrc) {
    asm volatile("{ .reg .u64 gp; cvta.to.global.u64 gp, %1;"
                 "  cp.async.cg.shared.global [%0], [gp], 16; }"
                 :: "r"(sdst), "l"(gsrc) : "memory");
}

static __device__ __forceinline__ void ldsm_x4(uint32_t* r, uint32_t addr) {
    asm volatile("ldmatrix.sync.aligned.m8n8.x4.shared.b16 {%0,%1,%2,%3}, [%4];"
                 : "=r"(r[0]), "=r"(r[1]), "=r"(r[2]), "=r"(r[3]) : "r"(addr));
}

static __device__ __forceinline__ uint32_t mul_bf16x2(uint32_t a, uint32_t b) {
    uint32_t r;
    asm("mul.rn.bf16x2 %0, %1, %2;" : "=r"(r) : "r"(a), "r"(b));
    return r;
}

static __device__ __forceinline__ void mma16816(float* c, const uint32_t* a,
                                                uint32_t b0, uint32_t b1) {
    asm volatile(
        "mma.sync.aligned.m16n8k16.row.col.f32.bf16.bf16.f32 "
        "{%0,%1,%2,%3}, {%4,%5,%6,%7}, {%8,%9}, {%0,%1,%2,%3};"
        : "+f"(c[0]), "+f"(c[1]), "+f"(c[2]), "+f"(c[3])
        : "r"(a[0]), "r"(a[1]), "r"(a[2]), "r"(a[3]), "r"(b0), "r"(b1));
}

static __device__ __forceinline__ uint16_t f2bf(float f) {
    __nv_bfloat16 h = __float2bfloat16(f);
    return *reinterpret_cast<uint16_t*>(&h);
}

// ---------------------------------------------------------------------------
// Kernel 1: coalesced pack of weight (IND,OUTD,25) -> g_W[o][d*512+i] + bias
// grid = (32 i-blocks of 16, 4 o-blocks of 128), block = 256
// smem transpose: s[o][d][i16] bf16, 102400 B dynamic
// ---------------------------------------------------------------------------
__global__ void __launch_bounds__(256, 1)
pack_W_kernel(const float* __restrict__ w, const float* __restrict__ bias)
{
    extern __shared__ __nv_bfloat16 s[];   // [128 o][25 d][16 i]
    const int t  = threadIdx.x;
    const int i0 = blockIdx.x * 16;
    const int o0 = blockIdx.y * 128;

    // Load: for each i, region w[(i0+i)*512 + o0 ... +128 rows x 25 d] is
    // 3200 contiguous floats (12.8KB) -> 800 float4, perfectly coalesced.
#pragma unroll 1
    for (int i = 0; i < 16; ++i) {
        const float4* src = reinterpret_cast<const float4*>(
            w + ((size_t)(i0 + i) * OUTD + o0) * D2);
        for (int f = t; f < 800; f += 256) {
            const float4 v = src[f];
            const int e0 = f * 4;
#pragma unroll
            for (int q = 0; q < 4; ++q) {
                const int e = e0 + q;
                const int o = e / 25;
                const int d = e - o * 25;
                const float val = (q == 0) ? v.x : (q == 1) ? v.y : (q == 2) ? v.z : v.w;
                s[((o * 25 + d) << 4) + i] = __float2bfloat16(val);
            }
        }
    }
    __syncthreads();

    // Store: each (o,d) pair owns 16 bf16 = 32B = TWO uint4 units.
    // p indexes 16B units: pair = p>>1, half = p&1.
    const uint4* sv = reinterpret_cast<const uint4*>(s);
    for (int p = t; p < 128 * 25 * 2; p += 256) {
        const int pair = p >> 1;
        const int hi   = p & 1;
        const int o = pair / 25;
        const int d = pair - o * 25;
        *reinterpret_cast<uint4*>(
            g_W + (size_t)(o0 + o) * KPAD + d * 512 + i0 + hi * 8) = sv[p];
    }

    // Bias block (cols 12800..12863), done by i-block 0 only
    if (blockIdx.x == 0) {
        for (int p = t; p < 128 * 64; p += 256) {
            const int o = p >> 6;
            const int cc = p & 63;
            __nv_bfloat16 val = __float2bfloat16(
                cc < D2 ? bias[(size_t)(o0 + o) * D2 + cc] : 0.0f);
            g_W[(size_t)(o0 + o) * KPAD + KREAL + cc] = val;
        }
    }
}

// ---------------------------------------------------------------------------
// Kernel 2: factorized-A HMMA GEMM.
// A[b, 64c+j] = kb[b, c>>3] * xf[b, (c&7)*64 + j]   (c < 200)
// A[b, 12800+j] = kbpad[b, j]                        (c == 200, bias)
// xf resident in smem (128KB, 8 SW128 sub-tiles); only B streams (cp.async,
// 4 stages x 16KB). Warps 0-3 even chunks / 4-7 odd chunks (k-split),
// partials reduced through smem; fused ReLU epilogue.
// grid = (32, 4), block = 256
// ---------------------------------------------------------------------------
__global__ void __launch_bounds__(256, 1)
gemm_hmma_kernel(const float* __restrict__ x, float* __restrict__ out)
{
    extern __shared__ char smem[];
    const uint32_t sb = smem_u32(smem);
    const int tid  = threadIdx.x;
    const int wid  = tid >> 5;
    const int lid  = tid & 31;
    const int m0   = blockIdx.x * TILE_M;
    const int n0   = blockIdx.y * TILE_N;
    const int wq   = wid & 3;        // spatial warp 0..3
    const int half = wid >> 2;       // k-split half (0: even chunks, 1: odd)
    const int wm   = wq >> 1;
    const int wn   = wq & 1;

    // ======================= prologue: build smem state =====================
    // xf: 128 rows x 512 cols bf16 as 8 blocks [ib][row][64 cols], SW128.
    {
        for (int f = tid; f < 128 * 256; f += 256) {      // float2 units
            const int row = f >> 8;
            const int c2  = f & 255;
            const int i   = c2 * 2;
            const float2 v = *reinterpret_cast<const float2*>(
                x + (size_t)(m0 + row) * ROWLEN + 2 + i);
            const uint32_t pk = (uint32_t)f2bf(v.x) | ((uint32_t)f2bf(v.y) << 16);
            const int ib = i >> 6;
            const int cb = i & 63;
            const uint32_t off = OFF_XF + ib * 16384 + row * 128 +
                                 (((uint32_t)(cb * 2)) ^ ((uint32_t)(row & 7) << 4));
            *reinterpret_cast<uint32_t*>(smem + off) = pk;
        }
    }
    // kb table + kbpad tile + x_treat passthrough
    if (tid < 128) {
        const float2 tt = *reinterpret_cast<const float2*>(
            x + (size_t)(m0 + tid) * ROWLEN);
        const float t0 = tt.x, t1 = tt.y;
        float u[5], v[5];
        u[0] = 1.0f; u[1] = t0; u[2] = t0 * t0;
        { float a = t0 - 0.33f; a = a > 0 ? a : 0; u[3] = a * a; }
        { float a = t0 - 0.66f; a = a > 0 ? a : 0; u[4] = a * a; }
        v[0] = 1.0f; v[1] = t1; v[2] = t1 * t1;
        { float a = t1 - 0.33f; a = a > 0 ? a : 0; v[3] = a * a; }
        { float a = t1 - 0.66f; a = a > 0 ? a : 0; v[4] = a * a; }

        __nv_bfloat16* kbs = reinterpret_cast<__nv_bfloat16*>(smem + OFF_KBS);
#pragma unroll
        for (int i = 0; i < 5; ++i)
#pragma unroll
            for (int j = 0; j < 5; ++j) {
                const int d = i * 5 + j;
                const float kv = u[i] * v[j];
                const uint16_t kb16 = f2bf(kv);
                kbs[d * 128 + tid] = *reinterpret_cast<const __nv_bfloat16*>(&kb16);
                // kbpad tile row=tid, col=d (swizzled)
                *reinterpret_cast<uint16_t*>(smem + OFF_KBP + tid * 128 +
                    (((uint32_t)(d * 2)) ^ ((uint32_t)(tid & 7) << 4))) = kb16;
            }
        // zero-fill kbpad cols 25..63
        for (int d = D2; d < 64; ++d)
            *reinterpret_cast<uint16_t*>(smem + OFF_KBP + tid * 128 +
                (((uint32_t)(d * 2)) ^ ((uint32_t)(tid & 7) << 4))) = 0;

        if (blockIdx.y == 0)
            *reinterpret_cast<float2*>(out + (size_t)(m0 + tid) * ROWLEN) = tt;
    }

    // ======================= B producer geometry ============================
    const int  pr0 = tid >> 3;                 // 0..31
    const int  pg  = tid & 7;
    const uint32_t psoff = (uint32_t)(pr0 * 128) +
                           ((uint32_t)(pg * 16) ^ (uint32_t)((pr0 & 7) << 4));
    const __nv_bfloat16* gB = g_W + (size_t)(n0 + pr0) * KPAD + pg * 8;

    // consumer geometry (ldmatrix lane addressing, SW128 swizzle)
    const int arow = wm * 64 + (lid & 15);
    const uint32_t a_sz = (uint32_t)((arow & 7) << 4);
    const uint32_t a_k  = (uint32_t)((lid >> 4) * 16);
    const int brow = wn * 64 + ((lid >> 4) << 3) + (lid & 7);
    const uint32_t b_sz = (uint32_t)((lid & 7) << 4);
    const uint32_t b_k  = (uint32_t)(((lid >> 3) & 1) * 16);

    float c[4][8][4];
#pragma unroll
    for (int mt = 0; mt < 4; ++mt)
#pragma unroll
        for (int nt = 0; nt < 8; ++nt)
#pragma unroll
            for (int i = 0; i < 4; ++i) c[mt][nt][i] = 0.0f;

    // prologue: fill B stages 0..2
#pragma unroll
    for (int s = 0; s < STAGES - 1; ++s) {
        const uint32_t dst = sb + OFF_BST + s * STAGE_B + psoff;
#pragma unroll
        for (int j = 0; j < 4; ++j)
            cp_async16(dst + j * 4096, gB + (size_t)s * 64 + (size_t)j * 32 * KPAD);
        asm volatile("cp.async.commit_group;" ::: "memory");
    }
    __syncthreads();   // also covers xf/kb smem population

    const __nv_bfloat16* kbs = reinterpret_cast<const __nv_bfloat16*>(smem + OFF_KBS);
    const int krow0 = wm * 64 + (lid >> 2);   // fragment row within tile (+mt*16)

    // ============================ main loop =================================
    for (int it = 0; it < NITER; ++it) {
        const int s = it & (STAGES - 1);
        asm volatile("cp.async.wait_group %0;" :: "n"(STAGES - 2) : "memory");
        __syncthreads();

        const int fi = it + STAGES - 1;
        if (fi < NITER) {
            const uint32_t dst = sb + OFF_BST + (fi & (STAGES - 1)) * STAGE_B + psoff;
#pragma unroll
            for (int j = 0; j < 4; ++j)
                cp_async16(dst + j * 4096, gB + (size_t)fi * 64 + (size_t)j * 32 * KPAD);
        }
        asm volatile("cp.async.commit_group;" ::: "memory");

        if ((it & 1) == half) {
            const bool isBias = (it == 200);
            const uint32_t stA = isBias ? (sb + OFF_KBP)
                                        : (sb + OFF_XF + (it & 7) * 16384);
            const uint32_t stB = sb + OFF_BST + s * STAGE_B;

            // per-mt kb scale factors (bf16x2 broadcast)
            uint32_t kLo[4], kHi[4];
            if (isBias) {
#pragma unroll
                for (int mt = 0; mt < 4; ++mt) { kLo[mt] = 0x3F803F80u; kHi[mt] = 0x3F803F80u; }
            } else {
                const int d = it >> 3;
#pragma unroll
                for (int mt = 0; mt < 4; ++mt) {
                    const int r = krow0 + mt * 16;
                    const uint32_t klo = *reinterpret_cast<const uint16_t*>(kbs + d * 128 + r);
                    const uint32_t khi = *reinterpret_cast<const uint16_t*>(kbs + d * 128 + r + 8);
                    kLo[mt] = klo * 0x10001u;
                    kHi[mt] = khi * 0x10001u;
                }
            }

#pragma unroll
            for (int ks = 0; ks < 4; ++ks) {
                uint32_t a[4][4];
#pragma unroll
                for (int mt = 0; mt < 4; ++mt) {
                    ldsm_x4(a[mt], stA + (uint32_t)(arow + mt * 16) * 128 +
                                   (((uint32_t)(ks * 32) + a_k) ^ a_sz));
                    a[mt][0] = mul_bf16x2(a[mt][0], kLo[mt]);
                    a[mt][1] = mul_bf16x2(a[mt][1], kHi[mt]);
                    a[mt][2] = mul_bf16x2(a[mt][2], kLo[mt]);
                    a[mt][3] = mul_bf16x2(a[mt][3], kHi[mt]);
                }
                uint32_t b[4][4];
#pragma unroll
                for (int np = 0; np < 4; ++np)
                    ldsm_x4(b[np], stB + (uint32_t)(brow + np * 16) * 128 +
                                   (((uint32_t)(ks * 32) + b_k) ^ b_sz));
#pragma unroll
                for (int mt = 0; mt < 4; ++mt)
#pragma unroll
                    for (int np = 0; np < 4; ++np) {
                        mma16816(c[mt][2 * np],     a[mt], b[np][0], b[np][1]);
                        mma16816(c[mt][2 * np + 1], a[mt], b[np][2], b[np][3]);
                    }
            }
        }
    }

    // ---- k-split reduction through smem (B stage buffers are dead now)
    __syncthreads();
    float* sred = reinterpret_cast<float*>(smem + OFF_BST);
    if (half == 1) {
        float* dst = sred + (size_t)(wid - 4) * 4096 + lid;
#pragma unroll
        for (int mt = 0; mt < 4; ++mt)
#pragma unroll
            for (int nt = 0; nt < 8; ++nt)
#pragma unroll
                for (int i = 0; i < 4; ++i)
                    dst[(((mt * 8 + nt) * 4) + i) * 32] = c[mt][nt][i];
    }
    __syncthreads();

    if (half == 0) {
        const float* src = sred + (size_t)wid * 4096 + lid;
#pragma unroll
        for (int mt = 0; mt < 4; ++mt)
#pragma unroll
            for (int nt = 0; nt < 8; ++nt)
#pragma unroll
                for (int i = 0; i < 4; ++i)
                    c[mt][nt][i] += src[(((mt * 8 + nt) * 4) + i) * 32];

        // ---- fused ReLU epilogue
        const int rbase = m0 + wm * 64 + (lid >> 2);
        const int cbase = n0 + wn * 64 + ((lid & 3) << 1);
#pragma unroll
        for (int mt = 0; mt < 4; ++mt) {
            const int r = rbase + mt * 16;
#pragma unroll
            for (int nt = 0; nt < 8; ++nt) {
                const int cc = cbase + nt * 8;
                float2 v0, v1;
                v0.x = fmaxf(c[mt][nt][0], 0.0f);
                v0.y = fmaxf(c[mt][nt][1], 0.0f);
                v1.x = fmaxf(c[mt][nt][2], 0.0f);
                v1.y = fmaxf(c[mt][nt][3], 0.0f);
                *reinterpret_cast<float2*>(out + (size_t)r * ROWLEN + 2 + cc) = v0;
                *reinterpret_cast<float2*>(out + (size_t)(r + 8) * ROWLEN + 2 + cc) = v1;
            }
        }
    }
}

// ---------------------------------------------------------------------------
// Launch
// ---------------------------------------------------------------------------
extern "C" void kernel_launch(void* const* d_in, const int* in_sizes, int n_in,
                              void* d_out, int out_size)
{
    (void)in_sizes; (void)n_in; (void)out_size;
    const float* x    = (const float*)d_in[0];   // (4096, 514)
    const float* w    = (const float*)d_in[1];   // (512, 512, 25)
    const float* bias = (const float*)d_in[2];   // (512, 25)
    float* out = (float*)d_out;                  // (4096, 514)

    cudaFuncSetAttribute(pack_W_kernel,
                         cudaFuncAttributeMaxDynamicSharedMemorySize, 102400);
    cudaFuncSetAttribute(gemm_hmma_kernel,
                         cudaFuncAttributeMaxDynamicSharedMemorySize, SMEM_GEMM);

    pack_W_kernel<<<dim3(32, 4), 256, 102400>>>(w, bias);
    gemm_hmma_kernel<<<dim3(BATCH / TILE_M, OUTD / TILE_N), 256, SMEM_GEMM>>>(x, out);
}

// round 7
// speedup vs baseline: 1.0846x; 1.0727x over previous
#include <cuda_runtime.h>
#include <cuda_bf16.h>
#include <cstdint>
#include <cstddef>

// ---------------------------------------------------------------------------
// Problem constants
// ---------------------------------------------------------------------------
#define BATCH   4096
#define IND     512
#define OUTD    512
#define ROWLEN  514            // P + IND
#define D2      25             // D^P
#define KREAL   12800          // IND * D2
#define KPAD    12864          // KREAL + 64 (bias block) = 201*64
#define NITER   201            // KPAD / 64  (chunk c covers k = 64c .. 64c+63)
#define STAGES  4
#define TILE_M  128
#define TILE_N  128
#define STAGE_B 16384          // B tile per stage: 128 rows x 128B

// smem layout (bytes) for GEMM kernel
#define OFF_BST   0                       // B stages: 4 x 16384 = 65536
#define OFF_XF    65536                   // xf: 8 blocks x 16384 = 131072
#define OFF_KBP   196608                  // kb-pad ldmatrix tile: 16384
#define OFF_KBS   212992                  // kb scalars: 25*128*2 = 6400
#define SMEM_GEMM 219392

// Packed weight+bias, bf16 K-major: g_W[o][d*512+i], cols 12800..12824 = bias
__device__ __nv_bfloat16 g_W[(size_t)OUTD * KPAD];

// ---------------------------------------------------------------------------
// PTX helpers (base sm_103 ISA only)
// ---------------------------------------------------------------------------
static __device__ __forceinline__ uint32_t smem_u32(const void* p) {
    uint32_t a;
    asm("{ .reg .u64 t; cvta.to.shared.u64 t, %1; cvt.u32.u64 %0, t; }"
        : "=r"(a) : "l"(p));
    return a;
}

static __device__ __forceinline__ void cp_async16(uint32_t sdst, const void* gsrc) {
    asm volatile("{ .reg .u64 gp; cvta.to.global.u64 gp, %1;"
                 "  cp.async.cg.shared.global [%0], [gp], 16; }"
                 :: "r"(sdst), "l"(gsrc) : "memory");
}

static __device__ __forceinline__ void ldsm_x4(uint32_t* r, uint32_t addr) {
    asm volatile("ldmatrix.sync.aligned.m8n8.x4.shared.b16 {%0,%1,%2,%3}, [%4];"
                 : "=r"(r[0]), "=r"(r[1]), "=r"(r[2]), "=r"(r[3]) : "r"(addr));
}

static __device__ __forceinline__ uint32_t mul_bf16x2(uint32_t a, uint32_t b) {
    uint32_t r;
    asm("mul.rn.bf16x2 %0, %1, %2;" : "=r"(r) : "r"(a), "r"(b));
    return r;
}

static __device__ __forceinline__ void mma16816(float* c, const uint32_t* a,
                                                uint32_t b0, uint32_t b1) {
    asm volatile(
        "mma.sync.aligned.m16n8k16.row.col.f32.bf16.bf16.f32 "
        "{%0,%1,%2,%3}, {%4,%5,%6,%7}, {%8,%9}, {%0,%1,%2,%3};"
        : "+f"(c[0]), "+f"(c[1]), "+f"(c[2]), "+f"(c[3])
        : "r"(a[0]), "r"(a[1]), "r"(a[2]), "r"(a[3]), "r"(b0), "r"(b1));
}

static __device__ __forceinline__ uint16_t f2bf(float f) {
    __nv_bfloat16 h = __float2bfloat16(f);
    return *reinterpret_cast<uint16_t*>(&h);
}

// pack_W smem swizzle: XOR byte-offset bits [4:6] with (pair>>2)&7 to spread
// banks (raw pattern is 32-way conflicted: bank = 8*pair mod 32 is constant
// across a warp's store lanes).
static __device__ __forceinline__ uint32_t pk_swz(uint32_t off, int pair) {
    return off ^ (uint32_t)(((pair >> 2) & 7) << 4);
}

// ---------------------------------------------------------------------------
// Kernel 1: coalesced pack of weight (IND,OUTD,25) -> g_W[o][d*512+i] + bias
// grid = (32 i-blocks of 16, 4 o-blocks of 128), block = 256
// smem transpose: s[pair=o*25+d][16 i] bf16, bank-swizzled, 102400 B dynamic
// ---------------------------------------------------------------------------
__global__ void __launch_bounds__(256, 1)
pack_W_kernel(const float* __restrict__ w, const float* __restrict__ bias)
{
    extern __shared__ char sc[];           // 3200 pairs x 32B
    const int t  = threadIdx.x;
    const int i0 = blockIdx.x * 16;
    const int o0 = blockIdx.y * 128;

    // Load: for each i, region w[(i0+i)*512 + o0 ...] is 3200 contiguous
    // floats (12.8KB) -> 800 float4, perfectly coalesced.
#pragma unroll 1
    for (int i = 0; i < 16; ++i) {
        const float4* src = reinterpret_cast<const float4*>(
            w + ((size_t)(i0 + i) * OUTD + o0) * D2);
        for (int f = t; f < 800; f += 256) {
            const float4 v = src[f];
            const int e0 = f * 4;
#pragma unroll
            for (int q = 0; q < 4; ++q) {
                const int pair = e0 + q;                 // o*25+d
                const float val = (q == 0) ? v.x : (q == 1) ? v.y
                                 : (q == 2) ? v.z : v.w;
                const uint32_t off = pk_swz((uint32_t)pair * 32 + i * 2, pair);
                *reinterpret_cast<__nv_bfloat16*>(sc + off) = __float2bfloat16(val);
            }
        }
    }
    __syncthreads();

    // Store: each (o,d) pair owns 16 bf16 = 32B = two uint4 units.
    for (int p = t; p < 128 * 25 * 2; p += 256) {
        const int pair = p >> 1;
        const int hi   = p & 1;
        const int o = pair / 25;
        const int d = pair - o * 25;
        const uint32_t off = pk_swz((uint32_t)pair * 32 + hi * 16, pair);
        const uint4 v = *reinterpret_cast<const uint4*>(sc + off);
        *reinterpret_cast<uint4*>(
            g_W + (size_t)(o0 + o) * KPAD + d * 512 + i0 + hi * 8) = v;
    }

    // Bias block (cols 12800..12863), done by i-block 0 only
    if (blockIdx.x == 0) {
        for (int p = t; p < 128 * 64; p += 256) {
            const int o = p >> 6;
            const int cc = p & 63;
            __nv_bfloat16 val = __float2bfloat16(
                cc < D2 ? bias[(size_t)(o0 + o) * D2 + cc] : 0.0f);
            g_W[(size_t)(o0 + o) * KPAD + KREAL + cc] = val;
        }
    }
}

// ---------------------------------------------------------------------------
// Kernel 2: factorized-A HMMA GEMM.
// A[b, 64c+j] = kb[b, c>>3] * xf[b, (c&7)*64 + j]   (c < 200)
// A[b, 12800+j] = kbpad[b, j]                        (c == 200, bias)
// xf resident in smem (128KB, 8 SW128 sub-tiles); only B streams (cp.async,
// 4 stages x 16KB). ALL 8 warps compute every chunk: 2x4 warp grid, 64x32
// warp tiles, double-buffered fragments. Fused ReLU epilogue.
// grid = (32, 4), block = 256
// ---------------------------------------------------------------------------
__global__ void __launch_bounds__(256, 1)
gemm_hmma_kernel(const float* __restrict__ x, float* __restrict__ out)
{
    extern __shared__ char smem[];
    const uint32_t sb = smem_u32(smem);
    const int tid  = threadIdx.x;
    const int wid  = tid >> 5;
    const int lid  = tid & 31;
    const int m0   = blockIdx.x * TILE_M;
    const int n0   = blockIdx.y * TILE_N;
    const int wm   = wid >> 2;       // 0..1  (64-row band)
    const int wn   = wid & 3;        // 0..3  (32-col band)

    // ======================= prologue: build smem state =====================
    // xf: 128 rows x 512 cols bf16 as 8 blocks [ib][row][64 cols], SW128.
    for (int f = tid; f < 128 * 256; f += 256) {      // float2 units
        const int row = f >> 8;
        const int c2  = f & 255;
        const int i   = c2 * 2;
        const float2 v = *reinterpret_cast<const float2*>(
            x + (size_t)(m0 + row) * ROWLEN + 2 + i);
        const uint32_t pk = (uint32_t)f2bf(v.x) | ((uint32_t)f2bf(v.y) << 16);
        const int ib = i >> 6;
        const int cb = i & 63;
        const uint32_t off = OFF_XF + ib * 16384 + row * 128 +
                             (((uint32_t)(cb * 2)) ^ ((uint32_t)(row & 7) << 4));
        *reinterpret_cast<uint32_t*>(smem + off) = pk;
    }
    // kb table + kbpad tile + x_treat passthrough
    if (tid < 128) {
        const float2 tt = *reinterpret_cast<const float2*>(
            x + (size_t)(m0 + tid) * ROWLEN);
        const float t0 = tt.x, t1 = tt.y;
        float u[5], v[5];
        u[0] = 1.0f; u[1] = t0; u[2] = t0 * t0;
        { float a = t0 - 0.33f; a = a > 0 ? a : 0; u[3] = a * a; }
        { float a = t0 - 0.66f; a = a > 0 ? a : 0; u[4] = a * a; }
        v[0] = 1.0f; v[1] = t1; v[2] = t1 * t1;
        { float a = t1 - 0.33f; a = a > 0 ? a : 0; v[3] = a * a; }
        { float a = t1 - 0.66f; a = a > 0 ? a : 0; v[4] = a * a; }

        __nv_bfloat16* kbs = reinterpret_cast<__nv_bfloat16*>(smem + OFF_KBS);
#pragma unroll
        for (int i = 0; i < 5; ++i)
#pragma unroll
            for (int j = 0; j < 5; ++j) {
                const int d = i * 5 + j;
                const uint16_t kb16 = f2bf(u[i] * v[j]);
                kbs[d * 128 + tid] = *reinterpret_cast<const __nv_bfloat16*>(&kb16);
                *reinterpret_cast<uint16_t*>(smem + OFF_KBP + tid * 128 +
                    (((uint32_t)(d * 2)) ^ ((uint32_t)(tid & 7) << 4))) = kb16;
            }
        for (int d = D2; d < 64; ++d)
            *reinterpret_cast<uint16_t*>(smem + OFF_KBP + tid * 128 +
                (((uint32_t)(d * 2)) ^ ((uint32_t)(tid & 7) << 4))) = 0;

        if (blockIdx.y == 0)
            *reinterpret_cast<float2*>(out + (size_t)(m0 + tid) * ROWLEN) = tt;
    }

    // ======================= B producer geometry ============================
    const int  pr0 = tid >> 3;                 // 0..31
    const int  pg  = tid & 7;
    const uint32_t psoff = (uint32_t)(pr0 * 128) +
                           ((uint32_t)(pg * 16) ^ (uint32_t)((pr0 & 7) << 4));
    const __nv_bfloat16* gB = g_W + (size_t)(n0 + pr0) * KPAD + pg * 8;

    // consumer geometry (ldmatrix lane addressing, SW128 swizzle)
    const int arow = wm * 64 + (lid & 15);
    const uint32_t a_sz = (uint32_t)((arow & 7) << 4);
    const uint32_t a_k  = (uint32_t)((lid >> 4) * 16);
    const int brow = wn * 32 + ((lid >> 4) << 3) + (lid & 7);
    const uint32_t b_sz = (uint32_t)((lid & 7) << 4);
    const uint32_t b_k  = (uint32_t)(((lid >> 3) & 1) * 16);

    float c[4][4][4];
#pragma unroll
    for (int mt = 0; mt < 4; ++mt)
#pragma unroll
        for (int nt = 0; nt < 4; ++nt)
#pragma unroll
            for (int i = 0; i < 4; ++i) c[mt][nt][i] = 0.0f;

    // prologue: fill B stages 0..2
#pragma unroll
    for (int s = 0; s < STAGES - 1; ++s) {
        const uint32_t dst = sb + OFF_BST + s * STAGE_B + psoff;
#pragma unroll
        for (int j = 0; j < 4; ++j)
            cp_async16(dst + j * 4096, gB + (size_t)s * 64 + (size_t)j * 32 * KPAD);
        asm volatile("cp.async.commit_group;" ::: "memory");
    }
    __syncthreads();   // also covers xf/kb smem population

    const __nv_bfloat16* kbs = reinterpret_cast<const __nv_bfloat16*>(smem + OFF_KBS);
    const int krow0 = wm * 64 + (lid >> 2);   // fragment row within tile (+mt*16)

    uint32_t aF[2][4][4];
    uint32_t bF[2][2][4];

#define LOAD_FRAGS(buf, kk)                                                    \
    {   const uint32_t kof = (uint32_t)((kk) * 32);                            \
        _Pragma("unroll")                                                      \
        for (int mt = 0; mt < 4; ++mt)                                         \
            ldsm_x4(aF[buf][mt], stA + (uint32_t)(arow + mt * 16) * 128 +      \
                                 ((kof + a_k) ^ a_sz));                        \
        _Pragma("unroll")                                                      \
        for (int np = 0; np < 2; ++np)                                         \
            ldsm_x4(bF[buf][np], stB + (uint32_t)(brow + np * 16) * 128 +      \
                                 ((kof + b_k) ^ b_sz));                        \
    }

    // ============================ main loop =================================
    for (int it = 0; it < NITER; ++it) {
        const int s = it & (STAGES - 1);
        asm volatile("cp.async.wait_group %0;" :: "n"(STAGES - 2) : "memory");
        __syncthreads();

        const int fi = it + STAGES - 1;
        if (fi < NITER) {
            const uint32_t dst = sb + OFF_BST + (fi & (STAGES - 1)) * STAGE_B + psoff;
#pragma unroll
            for (int j = 0; j < 4; ++j)
                cp_async16(dst + j * 4096, gB + (size_t)fi * 64 + (size_t)j * 32 * KPAD);
        }
        asm volatile("cp.async.commit_group;" ::: "memory");

        const bool isBias = (it == 200);
        const uint32_t stA = isBias ? (sb + OFF_KBP)
                                    : (sb + OFF_XF + (it & 7) * 16384);
        const uint32_t stB = sb + OFF_BST + s * STAGE_B;

        // per-mt kb scale factors (bf16x2 broadcast)
        uint32_t kLo[4], kHi[4];
        if (isBias) {
#pragma unroll
            for (int mt = 0; mt < 4; ++mt) { kLo[mt] = 0x3F803F80u; kHi[mt] = 0x3F803F80u; }
        } else {
            const int d = it >> 3;
#pragma unroll
            for (int mt = 0; mt < 4; ++mt) {
                const int r = krow0 + mt * 16;
                const uint32_t klo = *reinterpret_cast<const uint16_t*>(kbs + d * 128 + r);
                const uint32_t khi = *reinterpret_cast<const uint16_t*>(kbs + d * 128 + r + 8);
                kLo[mt] = klo * 0x10001u;
                kHi[mt] = khi * 0x10001u;
            }
        }

        LOAD_FRAGS(0, 0);
#pragma unroll
        for (int ks = 0; ks < 4; ++ks) {
            const int cur = ks & 1;
            if (ks < 3) LOAD_FRAGS(cur ^ 1, ks + 1);
#pragma unroll
            for (int mt = 0; mt < 4; ++mt) {
                aF[cur][mt][0] = mul_bf16x2(aF[cur][mt][0], kLo[mt]);
                aF[cur][mt][1] = mul_bf16x2(aF[cur][mt][1], kHi[mt]);
                aF[cur][mt][2] = mul_bf16x2(aF[cur][mt][2], kLo[mt]);
                aF[cur][mt][3] = mul_bf16x2(aF[cur][mt][3], kHi[mt]);
            }
#pragma unroll
            for (int mt = 0; mt < 4; ++mt)
#pragma unroll
                for (int np = 0; np < 2; ++np) {
                    mma16816(c[mt][2 * np],     aF[cur][mt], bF[cur][np][0], bF[cur][np][1]);
                    mma16816(c[mt][2 * np + 1], aF[cur][mt], bF[cur][np][2], bF[cur][np][3]);
                }
        }
    }

    // ---- fused ReLU epilogue (no reduction needed: full K per warp)
    {
        const int rbase = m0 + wm * 64 + (lid >> 2);
        const int cbase = n0 + wn * 32 + ((lid & 3) << 1);
#pragma unroll
        for (int mt = 0; mt < 4; ++mt) {
            const int r = rbase + mt * 16;
#pragma unroll
            for (int nt = 0; nt < 4; ++nt) {
                const int cc = cbase + nt * 8;
                float2 v0, v1;
                v0.x = fmaxf(c[mt][nt][0], 0.0f);
                v0.y = fmaxf(c[mt][nt][1], 0.0f);
                v1.x = fmaxf(c[mt][nt][2], 0.0f);
                v1.y = fmaxf(c[mt][nt][3], 0.0f);
                *reinterpret_cast<float2*>(out + (size_t)r * ROWLEN + 2 + cc) = v0;
                *reinterpret_cast<float2*>(out + (size_t)(r + 8) * ROWLEN + 2 + cc) = v1;
            }
        }
    }
}

// ---------------------------------------------------------------------------
// Launch
// ---------------------------------------------------------------------------
extern "C" void kernel_launch(void* const* d_in, const int* in_sizes, int n_in,
                              void* d_out, int out_size)
{
    (void)in_sizes; (void)n_in; (void)out_size;
    const float* x    = (const float*)d_in[0];   // (4096, 514)
    const float* w    = (const float*)d_in[1];   // (512, 512, 25)
    const float* bias = (const float*)d_in[2];   // (512, 25)
    float* out = (float*)d_out;                  // (4096, 514)

    cudaFuncSetAttribute(pack_W_kernel,
                         cudaFuncAttributeMaxDynamicSharedMemorySize, 102400);
    cudaFuncSetAttribute(gemm_hmma_kernel,
                         cudaFuncAttributeMaxDynamicSharedMemorySize, SMEM_GEMM);

    pack_W_kernel<<<dim3(32, 4), 256, 102400>>>(w, bias);
    gemm_hmma_kernel<<<dim3(BATCH / TILE_M, OUTD / TILE_N), 256, SMEM_GEMM>>>(x, out);
}

// round 8
// speedup vs baseline: 1.1586x; 1.0683x over previous
#include <cuda_runtime.h>
#include <cuda_bf16.h>
#include <cstdint>
#include <cstddef>

// ---------------------------------------------------------------------------
// Problem constants
// ---------------------------------------------------------------------------
#define BATCH   4096
#define IND     512
#define OUTD    512
#define ROWLEN  514            // P + IND
#define D2      25             // D^P
#define KREAL   12800          // IND * D2
#define KPAD    12864          // KREAL + 64 (bias block) = 201*64
#define NITER   201            // K chunks; chunk c' = ib*25 + d (ib-major), 200 = bias
#define STAGES  4
#define TILE_M  128
#define TILE_N  128
#define STAGE_B 16384          // B tile per stage: 128 rows x 128B

// smem layout (bytes) for GEMM kernel
#define OFF_BST   0                       // B stages: 4 x 16384 = 65536
#define OFF_XF    65536                   // xf: 8 blocks x 16384 = 131072
#define OFF_KBP   196608                  // kb-pad ldmatrix tile: 16384
#define OFF_KBS   212992                  // kb scalars: 25*128*2 = 6400
#define SMEM_GEMM 219392

// Packed weight+bias, bf16, K-permuted ib-major:
//   g_W[o][ (ib*25+d)*64 + icol ] = W[i = ib*64+icol][o][d],  cols 12800.. = bias
__device__ __nv_bfloat16 g_W[(size_t)OUTD * KPAD];

// ---------------------------------------------------------------------------
// PTX helpers (base sm_103 ISA only)
// ---------------------------------------------------------------------------
static __device__ __forceinline__ uint32_t smem_u32(const void* p) {
    uint32_t a;
    asm("{ .reg .u64 t; cvta.to.shared.u64 t, %1; cvt.u32.u64 %0, t; }"
        : "=r"(a) : "l"(p));
    return a;
}

static __device__ __forceinline__ void cp_async16(uint32_t sdst, const void* gsrc) {
    asm volatile("{ .reg .u64 gp; cvta.to.global.u64 gp, %1;"
                 "  cp.async.cg.shared.global [%0], [gp], 16; }"
                 :: "r"(sdst), "l"(gsrc) : "memory");
}

static __device__ __forceinline__ void ldsm_x4(uint32_t* r, uint32_t addr) {
    asm volatile("ldmatrix.sync.aligned.m8n8.x4.shared.b16 {%0,%1,%2,%3}, [%4];"
                 : "=r"(r[0]), "=r"(r[1]), "=r"(r[2]), "=r"(r[3]) : "r"(addr));
}

static __device__ __forceinline__ uint32_t mul_bf16x2(uint32_t a, uint32_t b) {
    uint32_t r;
    asm("mul.rn.bf16x2 %0, %1, %2;" : "=r"(r) : "r"(a), "r"(b));
    return r;
}

static __device__ __forceinline__ void mma16816(float* c, const uint32_t* a,
                                                uint32_t b0, uint32_t b1) {
    asm volatile(
        "mma.sync.aligned.m16n8k16.row.col.f32.bf16.bf16.f32 "
        "{%0,%1,%2,%3}, {%4,%5,%6,%7}, {%8,%9}, {%0,%1,%2,%3};"
        : "+f"(c[0]), "+f"(c[1]), "+f"(c[2]), "+f"(c[3])
        : "r"(a[0]), "r"(a[1]), "r"(a[2]), "r"(a[3]), "r"(b0), "r"(b1));
}

static __device__ __forceinline__ uint16_t f2bf(float f) {
    __nv_bfloat16 h = __float2bfloat16(f);
    return *reinterpret_cast<uint16_t*>(&h);
}

// pack_W smem swizzle: XOR byte-offset bits [4:6] with (pair>>2)&7 to spread banks
static __device__ __forceinline__ uint32_t pk_swz(uint32_t off, int pair) {
    return off ^ (uint32_t)(((pair >> 2) & 7) << 4);
}

// ---------------------------------------------------------------------------
// Kernel 1: coalesced pack of weight (IND,OUTD,25) -> g_W (ib-major K) + bias
// grid = (32 i-blocks of 16, 4 o-blocks of 128), block = 256
// ---------------------------------------------------------------------------
__global__ void __launch_bounds__(256, 1)
pack_W_kernel(const float* __restrict__ w, const float* __restrict__ bias)
{
    extern __shared__ char sc[];           // 3200 pairs x 32B, bank-swizzled
    const int t  = threadIdx.x;
    const int i0 = blockIdx.x * 16;
    const int o0 = blockIdx.y * 128;
    const int ib   = i0 >> 6;              // 16-block never crosses a 64-boundary
    const int icol = i0 & 63;

    // Load: per i, w[(i0+i)*512 + o0 ...] = 3200 contiguous floats, coalesced.
#pragma unroll 1
    for (int i = 0; i < 16; ++i) {
        const float4* src = reinterpret_cast<const float4*>(
            w + ((size_t)(i0 + i) * OUTD + o0) * D2);
        for (int f = t; f < 800; f += 256) {
            const float4 v = src[f];
            const int e0 = f * 4;
#pragma unroll
            for (int q = 0; q < 4; ++q) {
                const int pair = e0 + q;                 // o*25+d
                const float val = (q == 0) ? v.x : (q == 1) ? v.y
                                 : (q == 2) ? v.z : v.w;
                const uint32_t off = pk_swz((uint32_t)pair * 32 + i * 2, pair);
                *reinterpret_cast<__nv_bfloat16*>(sc + off) = __float2bfloat16(val);
            }
        }
    }
    __syncthreads();

    // Store: each (o,d) pair owns 16 bf16 = 32B = two uint4 units.
    // K-permuted destination: chunk c' = ib*25 + d, column icol within chunk.
    for (int p = t; p < 128 * 25 * 2; p += 256) {
        const int pair = p >> 1;
        const int hi   = p & 1;
        const int o = pair / 25;
        const int d = pair - o * 25;
        const uint32_t off = pk_swz((uint32_t)pair * 32 + hi * 16, pair);
        const uint4 v = *reinterpret_cast<const uint4*>(sc + off);
        *reinterpret_cast<uint4*>(
            g_W + (size_t)(o0 + o) * KPAD +
            (ib * 25 + d) * 64 + icol + hi * 8) = v;
    }

    // Bias block (chunk 200 = cols 12800..12863), done by i-block 0 only
    if (blockIdx.x == 0) {
        for (int p = t; p < 128 * 64; p += 256) {
            const int o = p >> 6;
            const int cc = p & 63;
            __nv_bfloat16 val = __float2bfloat16(
                cc < D2 ? bias[(size_t)(o0 + o) * D2 + cc] : 0.0f);
            g_W[(size_t)(o0 + o) * KPAD + KREAL + cc] = val;
        }
    }
}

// ---------------------------------------------------------------------------
// Kernel 2: factorized-A HMMA GEMM, ib-major K order.
// Chunk c' = ib*25+d (< 200): A = kb[.,d] * xf[., ib*64..]; chunk 200: kbpad.
// Raw xf fragments live in REGISTERS, reloaded via LDSM once per ib (8x total)
// -> per-chunk smem traffic is B-only (32KB/SM), tensor pipe becomes limiter.
// 2x4 warp grid, 64x32 warp tiles, double-buffered B frags, fused ReLU.
// grid = (32, 4), block = 256
// ---------------------------------------------------------------------------
__global__ void __launch_bounds__(256, 1)
gemm_hmma_kernel(const float* __restrict__ x, float* __restrict__ out)
{
    extern __shared__ char smem[];
    const uint32_t sb = smem_u32(smem);
    const int tid  = threadIdx.x;
    const int wid  = tid >> 5;
    const int lid  = tid & 31;
    const int m0   = blockIdx.x * TILE_M;
    const int n0   = blockIdx.y * TILE_N;
    const int wm   = wid >> 2;       // 0..1  (64-row band)
    const int wn   = wid & 3;        // 0..3  (32-col band)

    // ======================= prologue: build smem state =====================
    // xf: 128 rows x 512 cols bf16 as 8 blocks [ib][row][64 cols], SW128.
    for (int f = tid; f < 128 * 256; f += 256) {      // float2 units
        const int row = f >> 8;
        const int c2  = f & 255;
        const int i   = c2 * 2;
        const float2 v = *reinterpret_cast<const float2*>(
            x + (size_t)(m0 + row) * ROWLEN + 2 + i);
        const uint32_t pk = (uint32_t)f2bf(v.x) | ((uint32_t)f2bf(v.y) << 16);
        const int ib = i >> 6;
        const int cb = i & 63;
        const uint32_t off = OFF_XF + ib * 16384 + row * 128 +
                             (((uint32_t)(cb * 2)) ^ ((uint32_t)(row & 7) << 4));
        *reinterpret_cast<uint32_t*>(smem + off) = pk;
    }
    // kb table + kbpad tile + x_treat passthrough
    if (tid < 128) {
        const float2 tt = *reinterpret_cast<const float2*>(
            x + (size_t)(m0 + tid) * ROWLEN);
        const float t0 = tt.x, t1 = tt.y;
        float u[5], v[5];
        u[0] = 1.0f; u[1] = t0; u[2] = t0 * t0;
        { float a = t0 - 0.33f; a = a > 0 ? a : 0; u[3] = a * a; }
        { float a = t0 - 0.66f; a = a > 0 ? a : 0; u[4] = a * a; }
        v[0] = 1.0f; v[1] = t1; v[2] = t1 * t1;
        { float a = t1 - 0.33f; a = a > 0 ? a : 0; v[3] = a * a; }
        { float a = t1 - 0.66f; a = a > 0 ? a : 0; v[4] = a * a; }

        __nv_bfloat16* kbs = reinterpret_cast<__nv_bfloat16*>(smem + OFF_KBS);
#pragma unroll
        for (int i = 0; i < 5; ++i)
#pragma unroll
            for (int j = 0; j < 5; ++j) {
                const int d = i * 5 + j;
                const uint16_t kb16 = f2bf(u[i] * v[j]);
                kbs[d * 128 + tid] = *reinterpret_cast<const __nv_bfloat16*>(&kb16);
                *reinterpret_cast<uint16_t*>(smem + OFF_KBP + tid * 128 +
                    (((uint32_t)(d * 2)) ^ ((uint32_t)(tid & 7) << 4))) = kb16;
            }
        for (int d = D2; d < 64; ++d)
            *reinterpret_cast<uint16_t*>(smem + OFF_KBP + tid * 128 +
                (((uint32_t)(d * 2)) ^ ((uint32_t)(tid & 7) << 4))) = 0;

        if (blockIdx.y == 0)
            *reinterpret_cast<float2*>(out + (size_t)(m0 + tid) * ROWLEN) = tt;
    }

    // ======================= B producer geometry ============================
    const int  pr0 = tid >> 3;                 // 0..31
    const int  pg  = tid & 7;
    const uint32_t psoff = (uint32_t)(pr0 * 128) +
                           ((uint32_t)(pg * 16) ^ (uint32_t)((pr0 & 7) << 4));
    const __nv_bfloat16* gB = g_W + (size_t)(n0 + pr0) * KPAD + pg * 8;

    // consumer geometry (ldmatrix lane addressing, SW128 swizzle)
    const int arow = wm * 64 + (lid & 15);
    const uint32_t a_sz = (uint32_t)((arow & 7) << 4);
    const uint32_t a_k  = (uint32_t)((lid >> 4) * 16);
    const int brow = wn * 32 + ((lid >> 4) << 3) + (lid & 7);
    const uint32_t b_sz = (uint32_t)((lid & 7) << 4);
    const uint32_t b_k  = (uint32_t)(((lid >> 3) & 1) * 16);

    float c[4][4][4];
#pragma unroll
    for (int mt = 0; mt < 4; ++mt)
#pragma unroll
        for (int nt = 0; nt < 4; ++nt)
#pragma unroll
            for (int i = 0; i < 4; ++i) c[mt][nt][i] = 0.0f;

    // prologue: fill B stages 0..2
#pragma unroll
    for (int s = 0; s < STAGES - 1; ++s) {
        const uint32_t dst = sb + OFF_BST + s * STAGE_B + psoff;
#pragma unroll
        for (int j = 0; j < 4; ++j)
            cp_async16(dst + j * 4096, gB + (size_t)s * 64 + (size_t)j * 32 * KPAD);
        asm volatile("cp.async.commit_group;" ::: "memory");
    }
    __syncthreads();   // also covers xf/kb smem population

    const __nv_bfloat16* kbs = reinterpret_cast<const __nv_bfloat16*>(smem + OFF_KBS);
    const int krow0 = wm * 64 + (lid >> 2);   // fragment row within tile (+mt*16)

    uint32_t xfA[4][4][4];   // raw xf frags [ks][mt][reg], persists across d
    uint32_t aS[4][4];       // scaled frags for current ks
    uint32_t bF[2][2][4];    // B frags, double buffered

#define LOAD_XFA(base)                                                         \
    {   _Pragma("unroll")                                                      \
        for (int ks = 0; ks < 4; ++ks)                                         \
            _Pragma("unroll")                                                  \
            for (int mt = 0; mt < 4; ++mt)                                     \
                ldsm_x4(xfA[ks][mt], (base) + (uint32_t)(arow + mt * 16) * 128 \
                        + (((uint32_t)(ks * 32) + a_k) ^ a_sz));               \
    }

#define LOAD_B(buf, kk)                                                        \
    {   const uint32_t kof = (uint32_t)((kk) * 32);                            \
        _Pragma("unroll")                                                      \
        for (int np = 0; np < 2; ++np)                                         \
            ldsm_x4(bF[buf][np], stB + (uint32_t)(brow + np * 16) * 128 +      \
                                 ((kof + b_k) ^ b_sz));                        \
    }

    int dcnt = 0, ibc = 0;

    // ============================ main loop =================================
    for (int it = 0; it < NITER; ++it) {
        const int s = it & (STAGES - 1);
        asm volatile("cp.async.wait_group %0;" :: "n"(STAGES - 2) : "memory");
        __syncthreads();

        const int fi = it + STAGES - 1;
        if (fi < NITER) {
            const uint32_t dst = sb + OFF_BST + (fi & (STAGES - 1)) * STAGE_B + psoff;
#pragma unroll
            for (int j = 0; j < 4; ++j)
                cp_async16(dst + j * 4096, gB + (size_t)fi * 64 + (size_t)j * 32 * KPAD);
        }
        asm volatile("cp.async.commit_group;" ::: "memory");

        const uint32_t stB = sb + OFF_BST + s * STAGE_B;

        // per-mt kb scale factors (bf16x2 broadcast); refresh raw xf per ib
        uint32_t kLo[4], kHi[4];
        if (it == 200) {
            LOAD_XFA(sb + OFF_KBP);
#pragma unroll
            for (int mt = 0; mt < 4; ++mt) { kLo[mt] = 0x3F803F80u; kHi[mt] = 0x3F803F80u; }
        } else {
            if (dcnt == 0) LOAD_XFA(sb + OFF_XF + (uint32_t)ibc * 16384);
            const int d = dcnt;
#pragma unroll
            for (int mt = 0; mt < 4; ++mt) {
                const int r = krow0 + mt * 16;
                const uint32_t klo = *reinterpret_cast<const uint16_t*>(kbs + d * 128 + r);
                const uint32_t khi = *reinterpret_cast<const uint16_t*>(kbs + d * 128 + r + 8);
                kLo[mt] = klo * 0x10001u;
                kHi[mt] = khi * 0x10001u;
            }
            if (++dcnt == 25) { dcnt = 0; ++ibc; }
        }

        LOAD_B(0, 0);
#pragma unroll
        for (int ks = 0; ks < 4; ++ks) {
            const int cur = ks & 1;
            if (ks < 3) LOAD_B(cur ^ 1, ks + 1);
#pragma unroll
            for (int mt = 0; mt < 4; ++mt) {
                aS[mt][0] = mul_bf16x2(xfA[ks][mt][0], kLo[mt]);
                aS[mt][1] = mul_bf16x2(xfA[ks][mt][1], kHi[mt]);
                aS[mt][2] = mul_bf16x2(xfA[ks][mt][2], kLo[mt]);
                aS[mt][3] = mul_bf16x2(xfA[ks][mt][3], kHi[mt]);
            }
#pragma unroll
            for (int mt = 0; mt < 4; ++mt)
#pragma unroll
                for (int np = 0; np < 2; ++np) {
                    mma16816(c[mt][2 * np],     aS[mt], bF[cur][np][0], bF[cur][np][1]);
                    mma16816(c[mt][2 * np + 1], aS[mt], bF[cur][np][2], bF[cur][np][3]);
                }
        }
    }

    // ---- fused ReLU epilogue
    {
        const int rbase = m0 + wm * 64 + (lid >> 2);
        const int cbase = n0 + wn * 32 + ((lid & 3) << 1);
#pragma unroll
        for (int mt = 0; mt < 4; ++mt) {
            const int r = rbase + mt * 16;
#pragma unroll
            for (int nt = 0; nt < 4; ++nt) {
                const int cc = cbase + nt * 8;
                float2 v0, v1;
                v0.x = fmaxf(c[mt][nt][0], 0.0f);
                v0.y = fmaxf(c[mt][nt][1], 0.0f);
                v1.x = fmaxf(c[mt][nt][2], 0.0f);
                v1.y = fmaxf(c[mt][nt][3], 0.0f);
                *reinterpret_cast<float2*>(out + (size_t)r * ROWLEN + 2 + cc) = v0;
                *reinterpret_cast<float2*>(out + (size_t)(r + 8) * ROWLEN + 2 + cc) = v1;
            }
        }
    }
}

// ---------------------------------------------------------------------------
// Launch
// ---------------------------------------------------------------------------
extern "C" void kernel_launch(void* const* d_in, const int* in_sizes, int n_in,
                              void* d_out, int out_size)
{
    (void)in_sizes; (void)n_in; (void)out_size;
    const float* x    = (const float*)d_in[0];   // (4096, 514)
    const float* w    = (const float*)d_in[1];   // (512, 512, 25)
    const float* bias = (const float*)d_in[2];   // (512, 25)
    float* out = (float*)d_out;                  // (4096, 514)

    cudaFuncSetAttribute(pack_W_kernel,
                         cudaFuncAttributeMaxDynamicSharedMemorySize, 102400);
    cudaFuncSetAttribute(gemm_hmma_kernel,
                         cudaFuncAttributeMaxDynamicSharedMemorySize, SMEM_GEMM);

    pack_W_kernel<<<dim3(32, 4), 256, 102400>>>(w, bias);
    gemm_hmma_kernel<<<dim3(BATCH / TILE_M, OUTD / TILE_N), 256, SMEM_GEMM>>>(x, out);
}

// round 9
// speedup vs baseline: 1.1675x; 1.0077x over previous
#include <cuda_runtime.h>
#include <cuda_bf16.h>
#include <cstdint>
#include <cstddef>

// ---------------------------------------------------------------------------
// Problem constants
// ---------------------------------------------------------------------------
#define BATCH   4096
#define IND     512
#define OUTD    512
#define ROWLEN  514            // P + IND
#define D2      25             // D^P
#define KREAL   12800          // IND * D2
#define KPAD    12864          // KREAL + 64 (bias block) = 201*64
#define NITER   201            // K chunks; chunk c' = ib*25 + d (ib-major), 200 = bias
#define STAGES  4
#define TILE_M  128
#define TILE_N  128
#define STAGE_B 16384          // B tile per stage: 128 rows x 128B

// smem layout (bytes) for GEMM kernel
#define OFF_BST   0                       // B stages: 4 x 16384 = 65536
#define OFF_XF    65536                   // xf: 8 blocks x 16384 = 131072
#define OFF_KBP   196608                  // kb-pad ldmatrix tile: 16384
#define OFF_KBS   212992                  // kb scalars: 25*128*2 = 6400
#define SMEM_GEMM 219392

// Packed weight+bias, bf16, K-permuted ib-major:
//   g_W[o][ (ib*25+d)*64 + icol ] = W[i = ib*64+icol][o][d],  cols 12800.. = bias
__device__ __nv_bfloat16 g_W[(size_t)OUTD * KPAD];

// ---------------------------------------------------------------------------
// PTX helpers (base sm_103 ISA only)
// ---------------------------------------------------------------------------
static __device__ __forceinline__ uint32_t smem_u32(const void* p) {
    uint32_t a;
    asm("{ .reg .u64 t; cvta.to.shared.u64 t, %1; cvt.u32.u64 %0, t; }"
        : "=r"(a) : "l"(p));
    return a;
}

static __device__ __forceinline__ void cp_async16(uint32_t sdst, const void* gsrc) {
    asm volatile("{ .reg .u64 gp; cvta.to.global.u64 gp, %1;"
                 "  cp.async.cg.shared.global [%0], [gp], 16; }"
                 :: "r"(sdst), "l"(gsrc) : "memory");
}

static __device__ __forceinline__ void ldsm_x4(uint32_t* r, uint32_t addr) {
    asm volatile("ldmatrix.sync.aligned.m8n8.x4.shared.b16 {%0,%1,%2,%3}, [%4];"
                 : "=r"(r[0]), "=r"(r[1]), "=r"(r[2]), "=r"(r[3]) : "r"(addr));
}

static __device__ __forceinline__ uint32_t mul_bf16x2(uint32_t a, uint32_t b) {
    uint32_t r;
    asm("mul.rn.bf16x2 %0, %1, %2;" : "=r"(r) : "r"(a), "r"(b));
    return r;
}

static __device__ __forceinline__ void mma16816(float* c, const uint32_t* a,
                                                uint32_t b0, uint32_t b1) {
    asm volatile(
        "mma.sync.aligned.m16n8k16.row.col.f32.bf16.bf16.f32 "
        "{%0,%1,%2,%3}, {%4,%5,%6,%7}, {%8,%9}, {%0,%1,%2,%3};"
        : "+f"(c[0]), "+f"(c[1]), "+f"(c[2]), "+f"(c[3])
        : "r"(a[0]), "r"(a[1]), "r"(a[2]), "r"(a[3]), "r"(b0), "r"(b1));
}

static __device__ __forceinline__ uint16_t f2bf(float f) {
    __nv_bfloat16 h = __float2bfloat16(f);
    return *reinterpret_cast<uint16_t*>(&h);
}

// pack_W smem swizzle: XOR byte-offset bits [4:6] with (pair>>2)&7 to spread banks
static __device__ __forceinline__ uint32_t pk_swz(uint32_t off, int pair) {
    return off ^ (uint32_t)(((pair >> 2) & 7) << 4);
}

// ---------------------------------------------------------------------------
// Kernel 1: coalesced pack of weight (IND,OUTD,25) -> g_W (ib-major K) + bias
// grid = (32 i-blocks of 16, 4 o-blocks of 128), block = 256
// ---------------------------------------------------------------------------
__global__ void __launch_bounds__(256, 1)
pack_W_kernel(const float* __restrict__ w, const float* __restrict__ bias)
{
    extern __shared__ char sc[];           // 3200 pairs x 32B, bank-swizzled
    const int t  = threadIdx.x;
    const int i0 = blockIdx.x * 16;
    const int o0 = blockIdx.y * 128;
    const int ib   = i0 >> 6;              // 16-block never crosses a 64-boundary
    const int icol = i0 & 63;

    // Load: per i, w[(i0+i)*512 + o0 ...] = 3200 contiguous floats, coalesced.
#pragma unroll 1
    for (int i = 0; i < 16; ++i) {
        const float4* src = reinterpret_cast<const float4*>(
            w + ((size_t)(i0 + i) * OUTD + o0) * D2);
        for (int f = t; f < 800; f += 256) {
            const float4 v = src[f];
            const int e0 = f * 4;
#pragma unroll
            for (int q = 0; q < 4; ++q) {
                const int pair = e0 + q;                 // o*25+d
                const float val = (q == 0) ? v.x : (q == 1) ? v.y
                                 : (q == 2) ? v.z : v.w;
                const uint32_t off = pk_swz((uint32_t)pair * 32 + i * 2, pair);
                *reinterpret_cast<__nv_bfloat16*>(sc + off) = __float2bfloat16(val);
            }
        }
    }
    __syncthreads();

    // Store: each (o,d) pair owns 16 bf16 = 32B = two uint4 units.
    // K-permuted destination: chunk c' = ib*25 + d, column icol within chunk.
    for (int p = t; p < 128 * 25 * 2; p += 256) {
        const int pair = p >> 1;
        const int hi   = p & 1;
        const int o = pair / 25;
        const int d = pair - o * 25;
        const uint32_t off = pk_swz((uint32_t)pair * 32 + hi * 16, pair);
        const uint4 v = *reinterpret_cast<const uint4*>(sc + off);
        *reinterpret_cast<uint4*>(
            g_W + (size_t)(o0 + o) * KPAD +
            (ib * 25 + d) * 64 + icol + hi * 8) = v;
    }

    // Bias block (chunk 200 = cols 12800..12863), done by i-block 0 only
    if (blockIdx.x == 0) {
        for (int p = t; p < 128 * 64; p += 256) {
            const int o = p >> 6;
            const int cc = p & 63;
            __nv_bfloat16 val = __float2bfloat16(
                cc < D2 ? bias[(size_t)(o0 + o) * D2 + cc] : 0.0f);
            g_W[(size_t)(o0 + o) * KPAD + KREAL + cc] = val;
        }
    }
}

// ---------------------------------------------------------------------------
// Kernel 2: factorized-A HMMA GEMM, ib-major K order, 512 threads.
// Chunk c' = ib*25+d (< 200): A = kb[.,d] * xf[., ib*64..]; chunk 200: kbpad.
// 16 warps in a 4x4 grid of 32x32 warp tiles -> 4 warps/SMSP to hide
// HMMA/LDSM latency and barrier skew. Raw xf frags in registers per ib.
// grid = (32, 4), block = 512
// ---------------------------------------------------------------------------
__global__ void __launch_bounds__(512, 1)
gemm_hmma_kernel(const float* __restrict__ x, float* __restrict__ out)
{
    extern __shared__ char smem[];
    const uint32_t sb = smem_u32(smem);
    const int tid  = threadIdx.x;
    const int wid  = tid >> 5;
    const int lid  = tid & 31;
    const int m0   = blockIdx.x * TILE_M;
    const int n0   = blockIdx.y * TILE_N;
    const int wm   = wid >> 2;       // 0..3  (32-row band)
    const int wn   = wid & 3;        // 0..3  (32-col band)

    // ======================= prologue: build smem state =====================
    // xf: 128 rows x 512 cols bf16 as 8 blocks [ib][row][64 cols], SW128.
    for (int f = tid; f < 128 * 256; f += 512) {      // float2 units
        const int row = f >> 8;
        const int c2  = f & 255;
        const int i   = c2 * 2;
        const float2 v = *reinterpret_cast<const float2*>(
            x + (size_t)(m0 + row) * ROWLEN + 2 + i);
        const uint32_t pk = (uint32_t)f2bf(v.x) | ((uint32_t)f2bf(v.y) << 16);
        const int ib = i >> 6;
        const int cb = i & 63;
        const uint32_t off = OFF_XF + ib * 16384 + row * 128 +
                             (((uint32_t)(cb * 2)) ^ ((uint32_t)(row & 7) << 4));
        *reinterpret_cast<uint32_t*>(smem + off) = pk;
    }
    // kb table + kbpad tile + x_treat passthrough
    if (tid < 128) {
        const float2 tt = *reinterpret_cast<const float2*>(
            x + (size_t)(m0 + tid) * ROWLEN);
        const float t0 = tt.x, t1 = tt.y;
        float u[5], v[5];
        u[0] = 1.0f; u[1] = t0; u[2] = t0 * t0;
        { float a = t0 - 0.33f; a = a > 0 ? a : 0; u[3] = a * a; }
        { float a = t0 - 0.66f; a = a > 0 ? a : 0; u[4] = a * a; }
        v[0] = 1.0f; v[1] = t1; v[2] = t1 * t1;
        { float a = t1 - 0.33f; a = a > 0 ? a : 0; v[3] = a * a; }
        { float a = t1 - 0.66f; a = a > 0 ? a : 0; v[4] = a * a; }

        __nv_bfloat16* kbs = reinterpret_cast<__nv_bfloat16*>(smem + OFF_KBS);
#pragma unroll
        for (int i = 0; i < 5; ++i)
#pragma unroll
            for (int j = 0; j < 5; ++j) {
                const int d = i * 5 + j;
                const uint16_t kb16 = f2bf(u[i] * v[j]);
                kbs[d * 128 + tid] = *reinterpret_cast<const __nv_bfloat16*>(&kb16);
                *reinterpret_cast<uint16_t*>(smem + OFF_KBP + tid * 128 +
                    (((uint32_t)(d * 2)) ^ ((uint32_t)(tid & 7) << 4))) = kb16;
            }
        for (int d = D2; d < 64; ++d)
            *reinterpret_cast<uint16_t*>(smem + OFF_KBP + tid * 128 +
                (((uint32_t)(d * 2)) ^ ((uint32_t)(tid & 7) << 4))) = 0;

        if (blockIdx.y == 0)
            *reinterpret_cast<float2*>(out + (size_t)(m0 + tid) * ROWLEN) = tt;
    }

    // ======================= B producer geometry ============================
    // 512 threads, 16KB chunk = 1024 x 16B quanta: thread covers rows pr0, pr0+64.
    const int  pr0 = tid >> 3;                 // 0..63
    const int  pg  = tid & 7;
    const uint32_t psoff0 = (uint32_t)(pr0 * 128) +
                            ((uint32_t)(pg * 16) ^ (uint32_t)((pr0 & 7) << 4));
    const uint32_t psoff1 = (uint32_t)((pr0 + 64) * 128) +
                            ((uint32_t)(pg * 16) ^ (uint32_t)((pr0 & 7) << 4));
    const __nv_bfloat16* gB0 = g_W + (size_t)(n0 + pr0) * KPAD + pg * 8;
    const __nv_bfloat16* gB1 = g_W + (size_t)(n0 + pr0 + 64) * KPAD + pg * 8;

    // consumer geometry (ldmatrix lane addressing, SW128 swizzle)
    const int arow = wm * 32 + (lid & 15);
    const uint32_t a_sz = (uint32_t)((arow & 7) << 4);
    const uint32_t a_k  = (uint32_t)((lid >> 4) * 16);
    const int brow = wn * 32 + ((lid >> 4) << 3) + (lid & 7);
    const uint32_t b_sz = (uint32_t)((lid & 7) << 4);
    const uint32_t b_k  = (uint32_t)(((lid >> 3) & 1) * 16);

    float c[2][4][4];
#pragma unroll
    for (int mt = 0; mt < 2; ++mt)
#pragma unroll
        for (int nt = 0; nt < 4; ++nt)
#pragma unroll
            for (int i = 0; i < 4; ++i) c[mt][nt][i] = 0.0f;

    // prologue: fill B stages 0..2
#pragma unroll
    for (int s = 0; s < STAGES - 1; ++s) {
        const uint32_t dst = sb + OFF_BST + s * STAGE_B;
        cp_async16(dst + psoff0, gB0 + (size_t)s * 64);
        cp_async16(dst + psoff1, gB1 + (size_t)s * 64);
        asm volatile("cp.async.commit_group;" ::: "memory");
    }
    __syncthreads();   // also covers xf/kb smem population

    const __nv_bfloat16* kbs = reinterpret_cast<const __nv_bfloat16*>(smem + OFF_KBS);
    const int krow0 = wm * 32 + (lid >> 2);   // fragment row within tile (+mt*16)

    uint32_t xfA[4][2][4];   // raw xf frags [ks][mt][reg], persists across d
    uint32_t aS[2][4];       // scaled frags for current ks
    uint32_t bF[2][2][4];    // B frags, double buffered

#define LOAD_XFA(base)                                                         \
    {   _Pragma("unroll")                                                      \
        for (int ks = 0; ks < 4; ++ks)                                         \
            _Pragma("unroll")                                                  \
            for (int mt = 0; mt < 2; ++mt)                                     \
                ldsm_x4(xfA[ks][mt], (base) + (uint32_t)(arow + mt * 16) * 128 \
                        + (((uint32_t)(ks * 32) + a_k) ^ a_sz));               \
    }

#define LOAD_B(buf, kk)                                                        \
    {   const uint32_t kof = (uint32_t)((kk) * 32);                            \
        _Pragma("unroll")                                                      \
        for (int np = 0; np < 2; ++np)                                         \
            ldsm_x4(bF[buf][np], stB + (uint32_t)(brow + np * 16) * 128 +      \
                                 ((kof + b_k) ^ b_sz));                        \
    }

    int dcnt = 0, ibc = 0;

    // ============================ main loop =================================
    for (int it = 0; it < NITER; ++it) {
        const int s = it & (STAGES - 1);
        asm volatile("cp.async.wait_group %0;" :: "n"(STAGES - 2) : "memory");
        __syncthreads();

        const int fi = it + STAGES - 1;
        if (fi < NITER) {
            const uint32_t dst = sb + OFF_BST + (fi & (STAGES - 1)) * STAGE_B;
            cp_async16(dst + psoff0, gB0 + (size_t)fi * 64);
            cp_async16(dst + psoff1, gB1 + (size_t)fi * 64);
        }
        asm volatile("cp.async.commit_group;" ::: "memory");

        const uint32_t stB = sb + OFF_BST + s * STAGE_B;

        // per-mt kb scale factors (bf16x2 broadcast); refresh raw xf per ib
        uint32_t kLo[2], kHi[2];
        if (it == 200) {
            LOAD_XFA(sb + OFF_KBP);
#pragma unroll
            for (int mt = 0; mt < 2; ++mt) { kLo[mt] = 0x3F803F80u; kHi[mt] = 0x3F803F80u; }
        } else {
            if (dcnt == 0) LOAD_XFA(sb + OFF_XF + (uint32_t)ibc * 16384);
            const int d = dcnt;
#pragma unroll
            for (int mt = 0; mt < 2; ++mt) {
                const int r = krow0 + mt * 16;
                const uint32_t klo = *reinterpret_cast<const uint16_t*>(kbs + d * 128 + r);
                const uint32_t khi = *reinterpret_cast<const uint16_t*>(kbs + d * 128 + r + 8);
                kLo[mt] = klo * 0x10001u;
                kHi[mt] = khi * 0x10001u;
            }
            if (++dcnt == 25) { dcnt = 0; ++ibc; }
        }

        LOAD_B(0, 0);
#pragma unroll
        for (int ks = 0; ks < 4; ++ks) {
            const int cur = ks & 1;
            if (ks < 3) LOAD_B(cur ^ 1, ks + 1);
#pragma unroll
            for (int mt = 0; mt < 2; ++mt) {
                aS[mt][0] = mul_bf16x2(xfA[ks][mt][0], kLo[mt]);
                aS[mt][1] = mul_bf16x2(xfA[ks][mt][1], kHi[mt]);
                aS[mt][2] = mul_bf16x2(xfA[ks][mt][2], kLo[mt]);
                aS[mt][3] = mul_bf16x2(xfA[ks][mt][3], kHi[mt]);
            }
#pragma unroll
            for (int mt = 0; mt < 2; ++mt)
#pragma unroll
                for (int np = 0; np < 2; ++np) {
                    mma16816(c[mt][2 * np],     aS[mt], bF[cur][np][0], bF[cur][np][1]);
                    mma16816(c[mt][2 * np + 1], aS[mt], bF[cur][np][2], bF[cur][np][3]);
                }
        }
    }

    // ---- fused ReLU epilogue
    {
        const int rbase = m0 + wm * 32 + (lid >> 2);
        const int cbase = n0 + wn * 32 + ((lid & 3) << 1);
#pragma unroll
        for (int mt = 0; mt < 2; ++mt) {
            const int r = rbase + mt * 16;
#pragma unroll
            for (int nt = 0; nt < 4; ++nt) {
                const int cc = cbase + nt * 8;
                float2 v0, v1;
                v0.x = fmaxf(c[mt][nt][0], 0.0f);
                v0.y = fmaxf(c[mt][nt][1], 0.0f);
                v1.x = fmaxf(c[mt][nt][2], 0.0f);
                v1.y = fmaxf(c[mt][nt][3], 0.0f);
                *reinterpret_cast<float2*>(out + (size_t)r * ROWLEN + 2 + cc) = v0;
                *reinterpret_cast<float2*>(out + (size_t)(r + 8) * ROWLEN + 2 + cc) = v1;
            }
        }
    }
}

// ---------------------------------------------------------------------------
// Launch
// ---------------------------------------------------------------------------
extern "C" void kernel_launch(void* const* d_in, const int* in_sizes, int n_in,
                              void* d_out, int out_size)
{
    (void)in_sizes; (void)n_in; (void)out_size;
    const float* x    = (const float*)d_in[0];   // (4096, 514)
    const float* w    = (const float*)d_in[1];   // (512, 512, 25)
    const float* bias = (const float*)d_in[2];   // (512, 25)
    float* out = (float*)d_out;                  // (4096, 514)

    cudaFuncSetAttribute(pack_W_kernel,
                         cudaFuncAttributeMaxDynamicSharedMemorySize, 102400);
    cudaFuncSetAttribute(gemm_hmma_kernel,
                         cudaFuncAttributeMaxDynamicSharedMemorySize, SMEM_GEMM);

    pack_W_kernel<<<dim3(32, 4), 256, 102400>>>(w, bias);
    gemm_hmma_kernel<<<dim3(BATCH / TILE_M, OUTD / TILE_N), 512, SMEM_GEMM>>>(x, out);
}

// round 10
// speedup vs baseline: 1.1736x; 1.0052x over previous
#include <cuda_runtime.h>
#include <cuda_bf16.h>
#include <cstdint>
#include <cstddef>

// ---------------------------------------------------------------------------
// Problem constants
// ---------------------------------------------------------------------------
#define BATCH   4096
#define IND     512
#define OUTD    512
#define ROWLEN  514            // P + IND
#define D2      25             // D^P
#define KREAL   12800          // IND * D2
#define KPAD    12864          // KREAL + 64 (bias block) = 201*64
#define NITER   201            // K chunks; chunk c' = ib*25 + d (ib-major), 200 = bias
#define STAGES  4
#define TILE_M  128
#define TILE_N  128
#define STAGE_B 16384          // B tile per stage: 128 rows x 128B

// smem layout (bytes) for GEMM kernel
#define OFF_BST   0                       // B stages: 4 x 16384 = 65536
#define OFF_XF    65536                   // xf: 8 blocks x 16384 = 131072
#define OFF_KBP   196608                  // kb-pad ldmatrix tile: 16384
#define OFF_KBS   212992                  // kb scalars: 25*128*2 = 6400
#define SMEM_GEMM 219392

// Packed weight+bias, bf16, K-permuted ib-major:
//   g_W[o][ (ib*25+d)*64 + icol ] = W[i = ib*64+icol][o][d],  cols 12800.. = bias
__device__ __nv_bfloat16 g_W[(size_t)OUTD * KPAD];

// ---------------------------------------------------------------------------
// PTX helpers (base sm_103 ISA only)
// ---------------------------------------------------------------------------
static __device__ __forceinline__ uint32_t smem_u32(const void* p) {
    uint32_t a;
    asm("{ .reg .u64 t; cvta.to.shared.u64 t, %1; cvt.u32.u64 %0, t; }"
        : "=r"(a) : "l"(p));
    return a;
}

static __device__ __forceinline__ void cp_async16(uint32_t sdst, const void* gsrc) {
    asm volatile("{ .reg .u64 gp; cvta.to.global.u64 gp, %1;"
                 "  cp.async.cg.shared.global [%0], [gp], 16; }"
                 :: "r"(sdst), "l"(gsrc) : "memory");
}

static __device__ __forceinline__ void ldsm_x4(uint32_t* r, uint32_t addr) {
    asm volatile("ldmatrix.sync.aligned.m8n8.x4.shared.b16 {%0,%1,%2,%3}, [%4];"
                 : "=r"(r[0]), "=r"(r[1]), "=r"(r[2]), "=r"(r[3]) : "r"(addr));
}

static __device__ __forceinline__ uint32_t mul_bf16x2(uint32_t a, uint32_t b) {
    uint32_t r;
    asm("mul.rn.bf16x2 %0, %1, %2;" : "=r"(r) : "r"(a), "r"(b));
    return r;
}

static __device__ __forceinline__ void mma16816(float* c, const uint32_t* a,
                                                uint32_t b0, uint32_t b1) {
    asm volatile(
        "mma.sync.aligned.m16n8k16.row.col.f32.bf16.bf16.f32 "
        "{%0,%1,%2,%3}, {%4,%5,%6,%7}, {%8,%9}, {%0,%1,%2,%3};"
        : "+f"(c[0]), "+f"(c[1]), "+f"(c[2]), "+f"(c[3])
        : "r"(a[0]), "r"(a[1]), "r"(a[2]), "r"(a[3]), "r"(b0), "r"(b1));
}

static __device__ __forceinline__ uint16_t f2bf(float f) {
    __nv_bfloat16 h = __float2bfloat16(f);
    return *reinterpret_cast<uint16_t*>(&h);
}

// pack_W smem swizzle: XOR byte-offset bits [4:6] with (pair>>2)&7 to spread banks
static __device__ __forceinline__ uint32_t pk_swz(uint32_t off, int pair) {
    return off ^ (uint32_t)(((pair >> 2) & 7) << 4);
}

// ---------------------------------------------------------------------------
// Kernel 1: coalesced pack of weight (IND,OUTD,25) -> g_W (ib-major K) + bias
// grid = (32 i-blocks of 16, 4 o-blocks of 128), block = 256
// ---------------------------------------------------------------------------
__global__ void __launch_bounds__(256, 1)
pack_W_kernel(const float* __restrict__ w, const float* __restrict__ bias)
{
    extern __shared__ char sc[];           // 3200 pairs x 32B, bank-swizzled
    const int t  = threadIdx.x;
    const int i0 = blockIdx.x * 16;
    const int o0 = blockIdx.y * 128;
    const int ib   = i0 >> 6;              // 16-block never crosses a 64-boundary
    const int icol = i0 & 63;

    // Load: per i, w[(i0+i)*512 + o0 ...] = 3200 contiguous floats, coalesced.
#pragma unroll 1
    for (int i = 0; i < 16; ++i) {
        const float4* src = reinterpret_cast<const float4*>(
            w + ((size_t)(i0 + i) * OUTD + o0) * D2);
        for (int f = t; f < 800; f += 256) {
            const float4 v = src[f];
            const int e0 = f * 4;
#pragma unroll
            for (int q = 0; q < 4; ++q) {
                const int pair = e0 + q;                 // o*25+d
                const float val = (q == 0) ? v.x : (q == 1) ? v.y
                                 : (q == 2) ? v.z : v.w;
                const uint32_t off = pk_swz((uint32_t)pair * 32 + i * 2, pair);
                *reinterpret_cast<__nv_bfloat16*>(sc + off) = __float2bfloat16(val);
            }
        }
    }
    __syncthreads();

    // Store: each (o,d) pair owns 16 bf16 = 32B = two uint4 units.
    // K-permuted destination: chunk c' = ib*25 + d, column icol within chunk.
    for (int p = t; p < 128 * 25 * 2; p += 256) {
        const int pair = p >> 1;
        const int hi   = p & 1;
        const int o = pair / 25;
        const int d = pair - o * 25;
        const uint32_t off = pk_swz((uint32_t)pair * 32 + hi * 16, pair);
        const uint4 v = *reinterpret_cast<const uint4*>(sc + off);
        *reinterpret_cast<uint4*>(
            g_W + (size_t)(o0 + o) * KPAD +
            (ib * 25 + d) * 64 + icol + hi * 8) = v;
    }

    // Bias block (chunk 200 = cols 12800..12863), done by i-block 0 only
    if (blockIdx.x == 0) {
        for (int p = t; p < 128 * 64; p += 256) {
            const int o = p >> 6;
            const int cc = p & 63;
            __nv_bfloat16 val = __float2bfloat16(
                cc < D2 ? bias[(size_t)(o0 + o) * D2 + cc] : 0.0f);
            g_W[(size_t)(o0 + o) * KPAD + KREAL + cc] = val;
        }
    }
}

// ---------------------------------------------------------------------------
// Kernel 2: factorized-A HMMA GEMM, ib-major K order, 512 threads.
// Chunk c' = ib*25+d (< 200): A = kb[.,d] * xf[., ib*64..]; chunk 200: kbpad.
// 16 warps in a 4x4 grid of 32x32 warp tiles. Raw xf frags in registers per
// ib. B fragments TRIPLE-buffered with 2-phase-ahead LDSM prefetch so the
// smem crossbar time hides under HMMA time instead of serializing with it.
// grid = (32, 4), block = 512
// ---------------------------------------------------------------------------
__global__ void __launch_bounds__(512, 1)
gemm_hmma_kernel(const float* __restrict__ x, float* __restrict__ out)
{
    extern __shared__ char smem[];
    const uint32_t sb = smem_u32(smem);
    const int tid  = threadIdx.x;
    const int wid  = tid >> 5;
    const int lid  = tid & 31;
    const int m0   = blockIdx.x * TILE_M;
    const int n0   = blockIdx.y * TILE_N;
    const int wm   = wid >> 2;       // 0..3  (32-row band)
    const int wn   = wid & 3;        // 0..3  (32-col band)

    // ======================= prologue: build smem state =====================
    // xf: 128 rows x 512 cols bf16 as 8 blocks [ib][row][64 cols], SW128.
    for (int f = tid; f < 128 * 256; f += 512) {      // float2 units
        const int row = f >> 8;
        const int c2  = f & 255;
        const int i   = c2 * 2;
        const float2 v = *reinterpret_cast<const float2*>(
            x + (size_t)(m0 + row) * ROWLEN + 2 + i);
        const uint32_t pk = (uint32_t)f2bf(v.x) | ((uint32_t)f2bf(v.y) << 16);
        const int ib = i >> 6;
        const int cb = i & 63;
        const uint32_t off = OFF_XF + ib * 16384 + row * 128 +
                             (((uint32_t)(cb * 2)) ^ ((uint32_t)(row & 7) << 4));
        *reinterpret_cast<uint32_t*>(smem + off) = pk;
    }
    // kb table + kbpad tile + x_treat passthrough
    if (tid < 128) {
        const float2 tt = *reinterpret_cast<const float2*>(
            x + (size_t)(m0 + tid) * ROWLEN);
        const float t0 = tt.x, t1 = tt.y;
        float u[5], v[5];
        u[0] = 1.0f; u[1] = t0; u[2] = t0 * t0;
        { float a = t0 - 0.33f; a = a > 0 ? a : 0; u[3] = a * a; }
        { float a = t0 - 0.66f; a = a > 0 ? a : 0; u[4] = a * a; }
        v[0] = 1.0f; v[1] = t1; v[2] = t1 * t1;
        { float a = t1 - 0.33f; a = a > 0 ? a : 0; v[3] = a * a; }
        { float a = t1 - 0.66f; a = a > 0 ? a : 0; v[4] = a * a; }

        __nv_bfloat16* kbs = reinterpret_cast<__nv_bfloat16*>(smem + OFF_KBS);
#pragma unroll
        for (int i = 0; i < 5; ++i)
#pragma unroll
            for (int j = 0; j < 5; ++j) {
                const int d = i * 5 + j;
                const uint16_t kb16 = f2bf(u[i] * v[j]);
                kbs[d * 128 + tid] = *reinterpret_cast<const __nv_bfloat16*>(&kb16);
                *reinterpret_cast<uint16_t*>(smem + OFF_KBP + tid * 128 +
                    (((uint32_t)(d * 2)) ^ ((uint32_t)(tid & 7) << 4))) = kb16;
            }
        for (int d = D2; d < 64; ++d)
            *reinterpret_cast<uint16_t*>(smem + OFF_KBP + tid * 128 +
                (((uint32_t)(d * 2)) ^ ((uint32_t)(tid & 7) << 4))) = 0;

        if (blockIdx.y == 0)
            *reinterpret_cast<float2*>(out + (size_t)(m0 + tid) * ROWLEN) = tt;
    }

    // ======================= B producer geometry ============================
    // 512 threads, 16KB chunk = 1024 x 16B quanta: thread covers rows pr0, pr0+64.
    const int  pr0 = tid >> 3;                 // 0..63
    const int  pg  = tid & 7;
    const uint32_t psoff0 = (uint32_t)(pr0 * 128) +
                            ((uint32_t)(pg * 16) ^ (uint32_t)((pr0 & 7) << 4));
    const uint32_t psoff1 = (uint32_t)((pr0 + 64) * 128) +
                            ((uint32_t)(pg * 16) ^ (uint32_t)((pr0 & 7) << 4));
    const __nv_bfloat16* gB0 = g_W + (size_t)(n0 + pr0) * KPAD + pg * 8;
    const __nv_bfloat16* gB1 = g_W + (size_t)(n0 + pr0 + 64) * KPAD + pg * 8;

    // consumer geometry (ldmatrix lane addressing, SW128 swizzle)
    const int arow = wm * 32 + (lid & 15);
    const uint32_t a_sz = (uint32_t)((arow & 7) << 4);
    const uint32_t a_k  = (uint32_t)((lid >> 4) * 16);
    const int brow = wn * 32 + ((lid >> 4) << 3) + (lid & 7);
    const uint32_t b_sz = (uint32_t)((lid & 7) << 4);
    const uint32_t b_k  = (uint32_t)(((lid >> 3) & 1) * 16);

    float c[2][4][4];
#pragma unroll
    for (int mt = 0; mt < 2; ++mt)
#pragma unroll
        for (int nt = 0; nt < 4; ++nt)
#pragma unroll
            for (int i = 0; i < 4; ++i) c[mt][nt][i] = 0.0f;

    // prologue: fill B stages 0..2
#pragma unroll
    for (int s = 0; s < STAGES - 1; ++s) {
        const uint32_t dst = sb + OFF_BST + s * STAGE_B;
        cp_async16(dst + psoff0, gB0 + (size_t)s * 64);
        cp_async16(dst + psoff1, gB1 + (size_t)s * 64);
        asm volatile("cp.async.commit_group;" ::: "memory");
    }
    __syncthreads();   // also covers xf/kb smem population

    const __nv_bfloat16* kbs = reinterpret_cast<const __nv_bfloat16*>(smem + OFF_KBS);
    const int krow0 = wm * 32 + (lid >> 2);   // fragment row within tile (+mt*16)

    uint32_t xfA[4][2][4];   // raw xf frags [ks][mt][reg], persists across d
    uint32_t aS[2][4];       // scaled frags for current ks
    uint32_t bF[3][2][4];    // B frags, TRIPLE buffered (2-phase-ahead prefetch)

#define LOAD_XFA(base)                                                         \
    {   _Pragma("unroll")                                                      \
        for (int ks = 0; ks < 4; ++ks)                                         \
            _Pragma("unroll")                                                  \
            for (int mt = 0; mt < 2; ++mt)                                     \
                ldsm_x4(xfA[ks][mt], (base) + (uint32_t)(arow + mt * 16) * 128 \
                        + (((uint32_t)(ks * 32) + a_k) ^ a_sz));               \
    }

#define LOAD_B(buf, kk)                                                        \
    {   const uint32_t kof = (uint32_t)((kk) * 32);                            \
        _Pragma("unroll")                                                      \
        for (int np = 0; np < 2; ++np)                                         \
            ldsm_x4(bF[buf][np], stB + (uint32_t)(brow + np * 16) * 128 +      \
                                 ((kof + b_k) ^ b_sz));                        \
    }

    int dcnt = 0, ibc = 0;

    // ============================ main loop =================================
    for (int it = 0; it < NITER; ++it) {
        const int s = it & (STAGES - 1);
        asm volatile("cp.async.wait_group %0;" :: "n"(STAGES - 2) : "memory");
        __syncthreads();

        const int fi = it + STAGES - 1;
        if (fi < NITER) {
            const uint32_t dst = sb + OFF_BST + (fi & (STAGES - 1)) * STAGE_B;
            cp_async16(dst + psoff0, gB0 + (size_t)fi * 64);
            cp_async16(dst + psoff1, gB1 + (size_t)fi * 64);
        }
        asm volatile("cp.async.commit_group;" ::: "memory");

        const uint32_t stB = sb + OFF_BST + s * STAGE_B;

        // per-mt kb scale factors (bf16x2 broadcast); refresh raw xf per ib
        uint32_t kLo[2], kHi[2];
        if (it == 200) {
            LOAD_XFA(sb + OFF_KBP);
#pragma unroll
            for (int mt = 0; mt < 2; ++mt) { kLo[mt] = 0x3F803F80u; kHi[mt] = 0x3F803F80u; }
        } else {
            if (dcnt == 0) LOAD_XFA(sb + OFF_XF + (uint32_t)ibc * 16384);
            const int d = dcnt;
#pragma unroll
            for (int mt = 0; mt < 2; ++mt) {
                const int r = krow0 + mt * 16;
                const uint32_t klo = *reinterpret_cast<const uint16_t*>(kbs + d * 128 + r);
                const uint32_t khi = *reinterpret_cast<const uint16_t*>(kbs + d * 128 + r + 8);
                kLo[mt] = klo * 0x10001u;
                kHi[mt] = khi * 0x10001u;
            }
            if (++dcnt == 25) { dcnt = 0; ++ibc; }
        }

        // 2-phase-ahead B prefetch: LDSM for ks lands ~2 phases before use.
        LOAD_B(0, 0);
        LOAD_B(1, 1);
#pragma unroll
        for (int ks = 0; ks < 4; ++ks) {
            const int cur = ks % 3;
            if (ks < 2) LOAD_B((ks + 2) % 3, ks + 2);
#pragma unroll
            for (int mt = 0; mt < 2; ++mt) {
                aS[mt][0] = mul_bf16x2(xfA[ks][mt][0], kLo[mt]);
                aS[mt][1] = mul_bf16x2(xfA[ks][mt][1], kHi[mt]);
                aS[mt][2] = mul_bf16x2(xfA[ks][mt][2], kLo[mt]);
                aS[mt][3] = mul_bf16x2(xfA[ks][mt][3], kHi[mt]);
            }
#pragma unroll
            for (int mt = 0; mt < 2; ++mt)
#pragma unroll
                for (int np = 0; np < 2; ++np) {
                    mma16816(c[mt][2 * np],     aS[mt], bF[cur][np][0], bF[cur][np][1]);
                    mma16816(c[mt][2 * np + 1], aS[mt], bF[cur][np][2], bF[cur][np][3]);
                }
        }
    }

    // ---- fused ReLU epilogue
    {
        const int rbase = m0 + wm * 32 + (lid >> 2);
        const int cbase = n0 + wn * 32 + ((lid & 3) << 1);
#pragma unroll
        for (int mt = 0; mt < 2; ++mt) {
            const int r = rbase + mt * 16;
#pragma unroll
            for (int nt = 0; nt < 4; ++nt) {
                const int cc = cbase + nt * 8;
                float2 v0, v1;
                v0.x = fmaxf(c[mt][nt][0], 0.0f);
                v0.y = fmaxf(c[mt][nt][1], 0.0f);
                v1.x = fmaxf(c[mt][nt][2], 0.0f);
                v1.y = fmaxf(c[mt][nt][3], 0.0f);
                *reinterpret_cast<float2*>(out + (size_t)r * ROWLEN + 2 + cc) = v0;
                *reinterpret_cast<float2*>(out + (size_t)(r + 8) * ROWLEN + 2 + cc) = v1;
            }
        }
    }
}

// ---------------------------------------------------------------------------
// Launch
// ---------------------------------------------------------------------------
extern "C" void kernel_launch(void* const* d_in, const int* in_sizes, int n_in,
                              void* d_out, int out_size)
{
    (void)in_sizes; (void)n_in; (void)out_size;
    const float* x    = (const float*)d_in[0];   // (4096, 514)
    const float* w    = (const float*)d_in[1];   // (512, 512, 25)
    const float* bias = (const float*)d_in[2];   // (512, 25)
    float* out = (float*)d_out;                  // (4096, 514)

    cudaFuncSetAttribute(pack_W_kernel,
                         cudaFuncAttributeMaxDynamicSharedMemorySize, 102400);
    cudaFuncSetAttribute(gemm_hmma_kernel,
                         cudaFuncAttributeMaxDynamicSharedMemorySize, SMEM_GEMM);

    pack_W_kernel<<<dim3(32, 4), 256, 102400>>>(w, bias);
    gemm_hmma_kernel<<<dim3(BATCH / TILE_M, OUTD / TILE_N), 512, SMEM_GEMM>>>(x, out);
}

// round 11
// speedup vs baseline: 1.2602x; 1.0739x over previous
#include <cuda_runtime.h>
#include <cuda_bf16.h>
#include <cstdint>
#include <cstddef>

// ---------------------------------------------------------------------------
// Problem constants
// ---------------------------------------------------------------------------
#define BATCH   4096
#define IND     512
#define OUTD    512
#define ROWLEN  514            // P + IND
#define D2      25             // D^P
#define KPAD    12800          // IND * D2 (no bias block anymore)
#define NCH     200            // 64-wide K chunks, c' = ib*25 + d (ib-major)
#define TILE_M  128
#define TILE_N  128
#define STAGE_B 16384          // B tile per stage: 128 rows x 128B

// smem layout (bytes) for GEMM kernel
#define OFF_BST   0                       // B stages: 4 x 16384 = 65536
#define OFF_XF    65536                   // xf: 8 blocks x 16384 = 131072
#define OFF_KBF   196608                  // kb f32 table: 25*128*4 = 12800
#define SMEM_GEMM 209408

// Packed weight, bf16, K-permuted ib-major:
//   g_W[o][ (ib*25+d)*64 + icol ] = W[i = ib*64+icol][o][d]
__device__ __nv_bfloat16 g_W[(size_t)OUTD * KPAD];

// ---------------------------------------------------------------------------
// PTX helpers (base sm_103 ISA only)
// ---------------------------------------------------------------------------
static __device__ __forceinline__ uint32_t smem_u32(const void* p) {
    uint32_t a;
    asm("{ .reg .u64 t; cvta.to.shared.u64 t, %1; cvt.u32.u64 %0, t; }"
        : "=r"(a) : "l"(p));
    return a;
}

static __device__ __forceinline__ void cp_async16(uint32_t sdst, const void* gsrc) {
    asm volatile("{ .reg .u64 gp; cvta.to.global.u64 gp, %1;"
                 "  cp.async.cg.shared.global [%0], [gp], 16; }"
                 :: "r"(sdst), "l"(gsrc) : "memory");
}

static __device__ __forceinline__ void ldsm_x4(uint32_t* r, uint32_t addr) {
    asm volatile("ldmatrix.sync.aligned.m8n8.x4.shared.b16 {%0,%1,%2,%3}, [%4];"
                 : "=r"(r[0]), "=r"(r[1]), "=r"(r[2]), "=r"(r[3]) : "r"(addr));
}

static __device__ __forceinline__ uint32_t mul_bf16x2(uint32_t a, uint32_t b) {
    uint32_t r;
    asm("mul.rn.bf16x2 %0, %1, %2;" : "=r"(r) : "r"(a), "r"(b));
    return r;
}

static __device__ __forceinline__ void mma16816(float* c, const uint32_t* a,
                                                uint32_t b0, uint32_t b1) {
    asm volatile(
        "mma.sync.aligned.m16n8k16.row.col.f32.bf16.bf16.f32 "
        "{%0,%1,%2,%3}, {%4,%5,%6,%7}, {%8,%9}, {%0,%1,%2,%3};"
        : "+f"(c[0]), "+f"(c[1]), "+f"(c[2]), "+f"(c[3])
        : "r"(a[0]), "r"(a[1]), "r"(a[2]), "r"(a[3]), "r"(b0), "r"(b1));
}

static __device__ __forceinline__ uint16_t f2bf(float f) {
    __nv_bfloat16 h = __float2bfloat16(f);
    return *reinterpret_cast<uint16_t*>(&h);
}

// pack_W smem swizzle: XOR byte-offset bits [4:6] with (pair>>2)&7
static __device__ __forceinline__ uint32_t pk_swz(uint32_t off, int pair) {
    return off ^ (uint32_t)(((pair >> 2) & 7) << 4);
}

// ---------------------------------------------------------------------------
// Kernel 1: coalesced pack of weight (IND,OUTD,25) -> g_W (ib-major K)
// grid = (32 i-blocks of 16, 4 o-blocks of 128), block = 512
// ---------------------------------------------------------------------------
__global__ void __launch_bounds__(512, 1)
pack_W_kernel(const float* __restrict__ w)
{
    extern __shared__ char sc[];           // 3200 pairs x 32B, bank-swizzled
    const int t  = threadIdx.x;
    const int i0 = blockIdx.x * 16;
    const int o0 = blockIdx.y * 128;
    const int ib   = i0 >> 6;              // 16-block never crosses a 64-boundary
    const int icol = i0 & 63;

    // Load: per i, w[(i0+i)*512 + o0 ...] = 3200 contiguous floats, coalesced.
#pragma unroll 1
    for (int i = 0; i < 16; ++i) {
        const float4* src = reinterpret_cast<const float4*>(
            w + ((size_t)(i0 + i) * OUTD + o0) * D2);
        for (int f = t; f < 800; f += 512) {
            const float4 v = src[f];
            const int e0 = f * 4;
#pragma unroll
            for (int q = 0; q < 4; ++q) {
                const int pair = e0 + q;                 // o*25+d
                const float val = (q == 0) ? v.x : (q == 1) ? v.y
                                 : (q == 2) ? v.z : v.w;
                const uint32_t off = pk_swz((uint32_t)pair * 32 + i * 2, pair);
                *reinterpret_cast<__nv_bfloat16*>(sc + off) = __float2bfloat16(val);
            }
        }
    }
    __syncthreads();

    // Store: each (o,d) pair owns 16 bf16 = 32B = two uint4 units.
    for (int p = t; p < 128 * 25 * 2; p += 512) {
        const int pair = p >> 1;
        const int hi   = p & 1;
        const int o = pair / 25;
        const int d = pair - o * 25;
        const uint32_t off = pk_swz((uint32_t)pair * 32 + hi * 16, pair);
        const uint4 v = *reinterpret_cast<const uint4*>(sc + off);
        *reinterpret_cast<uint4*>(
            g_W + (size_t)(o0 + o) * KPAD +
            (ib * 25 + d) * 64 + icol + hi * 8) = v;
    }
}

// ---------------------------------------------------------------------------
// Kernel 2: factorized-A HMMA GEMM, ib-major K, 512 threads, 4x4 warp grid.
// 200 chunks; 2 chunks per epoch => ONE __syncthreads per 128 K.
// 4-stage pipeline, prefetch distance 2, always-commit (empty groups at tail).
// Bias added in an FFMA epilogue (kb f32 x smem-staged bias), then ReLU.
// grid = (32, 4), block = 512
// ---------------------------------------------------------------------------
__global__ void __launch_bounds__(512, 1)
gemm_hmma_kernel(const float* __restrict__ x, const float* __restrict__ bias,
                 float* __restrict__ out)
{
    extern __shared__ char smem[];
    const uint32_t sb = smem_u32(smem);
    const int tid  = threadIdx.x;
    const int wid  = tid >> 5;
    const int lid  = tid & 31;
    const int m0   = blockIdx.x * TILE_M;
    const int n0   = blockIdx.y * TILE_N;
    const int wm   = wid >> 2;       // 0..3  (32-row band)
    const int wn   = wid & 3;        // 0..3  (32-col band)

    // ======================= prologue: build smem state =====================
    // xf: 128 rows x 512 cols bf16 as 8 blocks [ib][row][64 cols], SW128.
    for (int f = tid; f < 128 * 256; f += 512) {      // float2 units
        const int row = f >> 8;
        const int c2  = f & 255;
        const int i   = c2 * 2;
        const float2 v = *reinterpret_cast<const float2*>(
            x + (size_t)(m0 + row) * ROWLEN + 2 + i);
        const uint32_t pk = (uint32_t)f2bf(v.x) | ((uint32_t)f2bf(v.y) << 16);
        const int ib = i >> 6;
        const int cb = i & 63;
        const uint32_t off = OFF_XF + ib * 16384 + row * 128 +
                             (((uint32_t)(cb * 2)) ^ ((uint32_t)(row & 7) << 4));
        *reinterpret_cast<uint32_t*>(smem + off) = pk;
    }
    // kb f32 table + x_treat passthrough
    if (tid < 128) {
        const float2 tt = *reinterpret_cast<const float2*>(
            x + (size_t)(m0 + tid) * ROWLEN);
        const float t0 = tt.x, t1 = tt.y;
        float u[5], v[5];
        u[0] = 1.0f; u[1] = t0; u[2] = t0 * t0;
        { float a = t0 - 0.33f; a = a > 0 ? a : 0; u[3] = a * a; }
        { float a = t0 - 0.66f; a = a > 0 ? a : 0; u[4] = a * a; }
        v[0] = 1.0f; v[1] = t1; v[2] = t1 * t1;
        { float a = t1 - 0.33f; a = a > 0 ? a : 0; v[3] = a * a; }
        { float a = t1 - 0.66f; a = a > 0 ? a : 0; v[4] = a * a; }

        float* kbf = reinterpret_cast<float*>(smem + OFF_KBF);
#pragma unroll
        for (int i = 0; i < 5; ++i)
#pragma unroll
            for (int j = 0; j < 5; ++j)
                kbf[(i * 5 + j) * 128 + tid] = u[i] * v[j];

        if (blockIdx.y == 0)
            *reinterpret_cast<float2*>(out + (size_t)(m0 + tid) * ROWLEN) = tt;
    }

    // ======================= B producer geometry ============================
    const int  pr0 = tid >> 3;                 // 0..63
    const int  pg  = tid & 7;
    const uint32_t psoff0 = (uint32_t)(pr0 * 128) +
                            ((uint32_t)(pg * 16) ^ (uint32_t)((pr0 & 7) << 4));
    const uint32_t psoff1 = (uint32_t)((pr0 + 64) * 128) +
                            ((uint32_t)(pg * 16) ^ (uint32_t)((pr0 & 7) << 4));
    const __nv_bfloat16* gB0 = g_W + (size_t)(n0 + pr0) * KPAD + pg * 8;
    const __nv_bfloat16* gB1 = g_W + (size_t)(n0 + pr0 + 64) * KPAD + pg * 8;

    // consumer geometry (ldmatrix lane addressing, SW128 swizzle)
    const int arow = wm * 32 + (lid & 15);
    const uint32_t a_sz = (uint32_t)((arow & 7) << 4);
    const uint32_t a_k  = (uint32_t)((lid >> 4) * 16);
    const int brow = wn * 32 + ((lid >> 4) << 3) + (lid & 7);
    const uint32_t b_sz = (uint32_t)((lid & 7) << 4);
    const uint32_t b_k  = (uint32_t)(((lid >> 3) & 1) * 16);

    float c[2][4][4];
#pragma unroll
    for (int mt = 0; mt < 2; ++mt)
#pragma unroll
        for (int nt = 0; nt < 4; ++nt)
#pragma unroll
            for (int i = 0; i < 4; ++i) c[mt][nt][i] = 0.0f;

    // prologue: prefetch chunks 0,1 -> stages 0,1 (one commit each)
#pragma unroll
    for (int f = 0; f < 2; ++f) {
        const uint32_t dst = sb + OFF_BST + f * STAGE_B;
        cp_async16(dst + psoff0, gB0 + (size_t)f * 64);
        cp_async16(dst + psoff1, gB1 + (size_t)f * 64);
        asm volatile("cp.async.commit_group;" ::: "memory");
    }
    __syncthreads();   // also covers xf/kbf smem population

    const float* kbf = reinterpret_cast<const float*>(smem + OFF_KBF);
    const int krow0 = wm * 32 + (lid >> 2);   // fragment row within tile (+mt*16)

    uint32_t xfA[4][2][4];   // raw xf frags [ks][mt][reg], persists across d
    uint32_t aS[2][4];       // scaled frags for current ks
    uint32_t bF[2][2][4];    // B frags, double buffered

#define LOAD_XFA(base)                                                         \
    {   _Pragma("unroll")                                                      \
        for (int ks = 0; ks < 4; ++ks)                                         \
            _Pragma("unroll")                                                  \
            for (int mt = 0; mt < 2; ++mt)                                     \
                ldsm_x4(xfA[ks][mt], (base) + (uint32_t)(arow + mt * 16) * 128 \
                        + (((uint32_t)(ks * 32) + a_k) ^ a_sz));               \
    }

#define LOAD_B(buf, kk)                                                        \
    {   const uint32_t kof = (uint32_t)((kk) * 32);                            \
        _Pragma("unroll")                                                      \
        for (int np = 0; np < 2; ++np)                                         \
            ldsm_x4(bF[buf][np], stB + (uint32_t)(brow + np * 16) * 128 +      \
                                 ((kof + b_k) ^ b_sz));                        \
    }

// consume one 64-K chunk from stage (f&3); d/ib tracked by caller counters
#define CONSUME(f, dcur, ibcur)                                                \
    {   const uint32_t stB = sb + OFF_BST + ((f) & 3) * STAGE_B;               \
        if ((dcur) == 0) LOAD_XFA(sb + OFF_XF + (uint32_t)(ibcur) * 16384);    \
        uint32_t kLo[2], kHi[2];                                               \
        _Pragma("unroll")                                                      \
        for (int mt = 0; mt < 2; ++mt) {                                       \
            const int r = krow0 + mt * 16;                                     \
            kLo[mt] = (uint32_t)f2bf(kbf[(dcur) * 128 + r]) * 0x10001u;        \
            kHi[mt] = (uint32_t)f2bf(kbf[(dcur) * 128 + r + 8]) * 0x10001u;    \
        }                                                                      \
        LOAD_B(0, 0);                                                          \
        _Pragma("unroll")                                                      \
        for (int ks = 0; ks < 4; ++ks) {                                       \
            const int cur = ks & 1;                                            \
            if (ks < 3) LOAD_B(cur ^ 1, ks + 1);                               \
            _Pragma("unroll")                                                  \
            for (int mt = 0; mt < 2; ++mt) {                                   \
                aS[mt][0] = mul_bf16x2(xfA[ks][mt][0], kLo[mt]);               \
                aS[mt][1] = mul_bf16x2(xfA[ks][mt][1], kHi[mt]);               \
                aS[mt][2] = mul_bf16x2(xfA[ks][mt][2], kLo[mt]);               \
                aS[mt][3] = mul_bf16x2(xfA[ks][mt][3], kHi[mt]);               \
            }                                                                  \
            _Pragma("unroll")                                                  \
            for (int mt = 0; mt < 2; ++mt)                                     \
                _Pragma("unroll")                                              \
                for (int np = 0; np < 2; ++np) {                               \
                    mma16816(c[mt][2*np],   aS[mt], bF[cur][np][0], bF[cur][np][1]); \
                    mma16816(c[mt][2*np+1], aS[mt], bF[cur][np][2], bF[cur][np][3]); \
                }                                                              \
        }                                                                      \
    }

    int dcnt = 0, ibc = 0;

    // ============ main loop: 2 chunks per epoch, 1 barrier per epoch ========
    for (int e = 0; e < NCH; e += 2) {
        // prefetch chunks e+2, e+3 (empty commits at tail keep groups counted)
#pragma unroll
        for (int k = 2; k < 4; ++k) {
            const int f = e + k;
            if (f < NCH) {
                const uint32_t dst = sb + OFF_BST + (f & 3) * STAGE_B;
                cp_async16(dst + psoff0, gB0 + (size_t)f * 64);
                cp_async16(dst + psoff1, gB1 + (size_t)f * 64);
            }
            asm volatile("cp.async.commit_group;" ::: "memory");
        }
        asm volatile("cp.async.wait_group %0;" :: "n"(2) : "memory");

        CONSUME(e, dcnt, ibc);
        if (++dcnt == 25) { dcnt = 0; ++ibc; }
        CONSUME(e + 1, dcnt, ibc);
        if (++dcnt == 25) { dcnt = 0; ++ibc; }

        __syncthreads();   // separates this epoch's reads from next's writes
    }

    // ================= bias epilogue: c += kb(f32) @ bias^T =================
    asm volatile("cp.async.wait_group %0;" :: "n"(0) : "memory");
    // stage bias[n0..n0+127][0..24] (contiguous 12.8KB) into stage-0 smem
    float* sbias = reinterpret_cast<float*>(smem + OFF_BST);
    {
        const float* gb = bias + (size_t)n0 * D2;
        for (int i = tid; i < 128 * D2; i += 512) sbias[i] = gb[i];
    }
    __syncthreads();

    {
        const int cb0 = wn * 32 + ((lid & 3) << 1);   // local col base
#pragma unroll 1
        for (int d = 0; d < D2; ++d) {
            float kbA[2], kbB[2];
#pragma unroll
            for (int mt = 0; mt < 2; ++mt) {
                const int r = krow0 + mt * 16;
                kbA[mt] = kbf[d * 128 + r];
                kbB[mt] = kbf[d * 128 + r + 8];
            }
#pragma unroll
            for (int nt = 0; nt < 4; ++nt) {
                const int cc = cb0 + nt * 8;
                const float b0 = sbias[cc * D2 + d];
                const float b1 = sbias[(cc + 1) * D2 + d];
#pragma unroll
                for (int mt = 0; mt < 2; ++mt) {
                    c[mt][nt][0] += kbA[mt] * b0;
                    c[mt][nt][1] += kbA[mt] * b1;
                    c[mt][nt][2] += kbB[mt] * b0;
                    c[mt][nt][3] += kbB[mt] * b1;
                }
            }
        }
    }

    // ---- fused ReLU epilogue
    {
        const int rbase = m0 + wm * 32 + (lid >> 2);
        const int cbase = n0 + wn * 32 + ((lid & 3) << 1);
#pragma unroll
        for (int mt = 0; mt < 2; ++mt) {
            const int r = rbase + mt * 16;
#pragma unroll
            for (int nt = 0; nt < 4; ++nt) {
                const int cc = cbase + nt * 8;
                float2 v0, v1;
                v0.x = fmaxf(c[mt][nt][0], 0.0f);
                v0.y = fmaxf(c[mt][nt][1], 0.0f);
                v1.x = fmaxf(c[mt][nt][2], 0.0f);
                v1.y = fmaxf(c[mt][nt][3], 0.0f);
                *reinterpret_cast<float2*>(out + (size_t)r * ROWLEN + 2 + cc) = v0;
                *reinterpret_cast<float2*>(out + (size_t)(r + 8) * ROWLEN + 2 + cc) = v1;
            }
        }
    }
}

// ---------------------------------------------------------------------------
// Launch
// ---------------------------------------------------------------------------
extern "C" void kernel_launch(void* const* d_in, const int* in_sizes, int n_in,
                              void* d_out, int out_size)
{
    (void)in_sizes; (void)n_in; (void)out_size;
    const float* x    = (const float*)d_in[0];   // (4096, 514)
    const float* w    = (const float*)d_in[1];   // (512, 512, 25)
    const float* bias = (const float*)d_in[2];   // (512, 25)
    float* out = (float*)d_out;                  // (4096, 514)

    cudaFuncSetAttribute(pack_W_kernel,
                         cudaFuncAttributeMaxDynamicSharedMemorySize, 102400);
    cudaFuncSetAttribute(gemm_hmma_kernel,
                         cudaFuncAttributeMaxDynamicSharedMemorySize, SMEM_GEMM);

    pack_W_kernel<<<dim3(32, 4), 512, 102400>>>(w);
    gemm_hmma_kernel<<<dim3(BATCH / TILE_M, OUTD / TILE_N), 512, SMEM_GEMM>>>(
        x, bias, out);
}